// round 4
// baseline (speedup 1.0000x reference)
#include <cuda_runtime.h>
#include <math.h>
#include <stdint.h>

#define BATCH   2
#define SEQ     2048
#define DMODEL  1024
#define NHEADS  16
#define DHEAD   64
#define INNER   1024        // NHEADS*DKV
#define QKV3    3072        // 3*INNER

// -------- scratch (device globals; no allocation allowed) --------
__device__ float g_qkv[(size_t)BATCH * SEQ * QKV3];   // 48 MB : [b*s][3072] (q|k|v)
__device__ float g_ai [(size_t)BATCH * SEQ * INNER];  // 16 MB : attention inner output
__device__ float g_bias[NHEADS * 4096];               // 256 KB: bias[h][ (k-q)+2048 ]

// ---------------------------------------------------------------------------
// 1) Fill per-delta bias table
// ---------------------------------------------------------------------------
__global__ void bias_fill_kernel(const float* __restrict__ table) {
    int idx = blockIdx.x * blockDim.x + threadIdx.x;  // 0..4095
    if (idx >= 4096) return;
    int rel = idx - 2048;                 // rel = k - q  (mem - ctx)
    int bucket = (rel > 0) ? 16 : 0;      // num_buckets//2 = 16
    int ad = rel < 0 ? -rel : rel;
    int bb;
    if (ad < 8) {
        bb = ad;
    } else {
        float rp = (float)ad;
        float l  = (float)log((double)(rp / 8.0f));     // correctly-rounded f32 log
        float v  = (l / 2.7725887f) * 8.0f;             // f32(log(16))
        bb = 8 + (int)v;
        if (bb > 15) bb = 15;
    }
    bucket += bb;
    #pragma unroll
    for (int h = 0; h < NHEADS; h++)
        g_bias[h * 4096 + idx] = table[bucket * NHEADS + h];
}

// ---------------------------------------------------------------------------
// 2) Write position_bias output [1,16,2048,2048]
// ---------------------------------------------------------------------------
__global__ void bias_write_kernel(float* __restrict__ out) {
    int q = blockIdx.x;
    int h = blockIdx.y;
    int k = threadIdx.x << 2;  // 512 threads * 4 = 2048
    const float* src = g_bias + h * 4096 + (2048 - q) + k;
    float4 v = make_float4(src[0], src[1], src[2], src[3]);
    *(float4*)(out + ((size_t)h * SEQ + q) * SEQ + k) = v;
}

// ---------------------------------------------------------------------------
// 3) Tensor-core GEMM: C[M,N] = A[M,K] @ B[K,N], 3xTF32 (fp32-quality)
//    128x128x8 tiles, double-buffered, 8 warps (2m x 4n), 64x32 warp tile
// ---------------------------------------------------------------------------
__device__ __forceinline__ void tf32_split(float x, uint32_t& hi, uint32_t& lo) {
    uint32_t h;
    asm("cvt.rna.tf32.f32 %0, %1;" : "=r"(h) : "f"(x));
    float r = x - __uint_as_float(h);
    uint32_t l;
    asm("cvt.rna.tf32.f32 %0, %1;" : "=r"(l) : "f"(r));
    hi = h; lo = l;
}

__device__ __forceinline__ void mma_tf32(float* d, const uint32_t* a, const uint32_t* b) {
    asm volatile(
        "mma.sync.aligned.m16n8k8.row.col.f32.tf32.tf32.f32 "
        "{%0,%1,%2,%3},{%4,%5,%6,%7},{%8,%9},{%0,%1,%2,%3};"
        : "+f"(d[0]), "+f"(d[1]), "+f"(d[2]), "+f"(d[3])
        : "r"(a[0]), "r"(a[1]), "r"(a[2]), "r"(a[3]), "r"(b[0]), "r"(b[1]));
}

#define AS_STRIDE 12    // 128 rows x (8 + pad) -> conflict-free A frag loads
#define BS_STRIDE 136   // 8 rows x (128 + pad) -> conflict-free B frag loads

__global__ __launch_bounds__(256) void gemm_tf32x3_kernel(
    const float* __restrict__ A, const float* __restrict__ B,
    float* __restrict__ C, int M, int N, int K)
{
    __shared__ float As[2][128 * AS_STRIDE];
    __shared__ float Bs[2][8 * BS_STRIDE];

    int tid  = threadIdx.x;
    int warp = tid >> 5, lane = tid & 31;
    int wm = warp & 1, wn = warp >> 1;     // 2 (m) x 4 (n)
    int bm = blockIdx.y << 7, bn = blockIdx.x << 7;

    // global load indices
    int ar = tid >> 1,  ac = (tid & 1) << 2;   // A tile: 128 x 8
    int br = tid >> 5,  bc = (tid & 31) << 2;  // B tile:   8 x 128
    const float* Ap = A + (size_t)(bm + ar) * K + ac;
    const float* Bp = B + (size_t)br * N + bn + bc;

    float acc[4][4][4];
    #pragma unroll
    for (int mi = 0; mi < 4; mi++)
        #pragma unroll
        for (int ni = 0; ni < 4; ni++)
            #pragma unroll
            for (int e = 0; e < 4; e++) acc[mi][ni][e] = 0.f;

    // preload first tile
    float4 a_v = *(const float4*)Ap;
    float4 b_v = *(const float4*)Bp;
    *(float4*)&As[0][ar * AS_STRIDE + ac] = a_v;
    *(float4*)&Bs[0][br * BS_STRIDE + bc] = b_v;
    __syncthreads();

    int frow = lane >> 2, fk = lane & 3;      // fragment row group / k index
    int buf = 0;

    for (int k0 = 8; k0 <= K; k0 += 8) {
        if (k0 < K) {
            a_v = *(const float4*)(Ap + k0);
            b_v = *(const float4*)(Bp + (size_t)k0 * N);
        }

        // ---- load + split fragments from smem buf ----
        uint32_t Ahi[4][4], Alo[4][4], Bhi[4][2], Blo[4][2];
        const float* as = As[buf];
        const float* bs = Bs[buf];
        #pragma unroll
        for (int mi = 0; mi < 4; mi++) {
            int r = (wm << 6) + (mi << 4) + frow;
            float a0 = as[r * AS_STRIDE + fk];
            float a1 = as[(r + 8) * AS_STRIDE + fk];
            float a2 = as[r * AS_STRIDE + fk + 4];
            float a3 = as[(r + 8) * AS_STRIDE + fk + 4];
            tf32_split(a0, Ahi[mi][0], Alo[mi][0]);
            tf32_split(a1, Ahi[mi][1], Alo[mi][1]);
            tf32_split(a2, Ahi[mi][2], Alo[mi][2]);
            tf32_split(a3, Ahi[mi][3], Alo[mi][3]);
        }
        #pragma unroll
        for (int ni = 0; ni < 4; ni++) {
            int n = (wn << 5) + (ni << 3) + frow;
            float b0 = bs[fk * BS_STRIDE + n];
            float b1 = bs[(fk + 4) * BS_STRIDE + n];
            tf32_split(b0, Bhi[ni][0], Blo[ni][0]);
            tf32_split(b1, Bhi[ni][1], Blo[ni][1]);
        }

        // ---- 3xTF32 MMAs ----
        #pragma unroll
        for (int mi = 0; mi < 4; mi++)
            #pragma unroll
            for (int ni = 0; ni < 4; ni++) {
                mma_tf32(acc[mi][ni], Ahi[mi], Blo[ni]);
                mma_tf32(acc[mi][ni], Alo[mi], Bhi[ni]);
                mma_tf32(acc[mi][ni], Ahi[mi], Bhi[ni]);
            }

        if (k0 < K) {
            *(float4*)&As[buf ^ 1][ar * AS_STRIDE + ac] = a_v;
            *(float4*)&Bs[buf ^ 1][br * BS_STRIDE + bc] = b_v;
        }
        __syncthreads();
        buf ^= 1;
    }

    // ---- epilogue ----
    #pragma unroll
    for (int mi = 0; mi < 4; mi++) {
        int r0 = bm + (wm << 6) + (mi << 4) + frow;
        #pragma unroll
        for (int ni = 0; ni < 4; ni++) {
            int c0 = bn + (wn << 5) + (ni << 3) + (fk << 1);
            *(float2*)&C[(size_t)r0 * N + c0]       = make_float2(acc[mi][ni][0], acc[mi][ni][1]);
            *(float2*)&C[(size_t)(r0 + 8) * N + c0] = make_float2(acc[mi][ni][2], acc[mi][ni][3]);
        }
    }
}

// ---------------------------------------------------------------------------
// 4) Flash attention (fp32), 64x64 tiles, 4x4 frags, bias from g_bias (L2)
// ---------------------------------------------------------------------------
__global__ __launch_bounds__(256, 2) void attn_kernel() {
    __shared__ float Qs[64 * 64];   // Q[row][d]
    __shared__ float KP[64 * 64];   // K^T[d][k] during S; then P[row][k] during PV
    __shared__ float Vs[64 * 64];   // V[k][d]

    int tid = threadIdx.x;
    int tx = tid & 15, ty = tid >> 4;
    int q0 = blockIdx.x << 6;
    int h  = blockIdx.y;
    int b  = blockIdx.z;
    size_t base = (size_t)b * SEQ * QKV3;

    const float* gb = g_bias + h * 4096 + 2048 - q0 + (tx << 2) - (ty << 2);

    #pragma unroll
    for (int j = 0; j < 4; j++) {
        int idx = (j << 8) + tid;
        int row = idx >> 4, c4 = (idx & 15) << 2;
        *(float4*)&Qs[(row << 6) + c4] =
            *(const float4*)&g_qkv[base + (size_t)(q0 + row) * QKV3 + h * DHEAD + c4];
    }

    float m_i[4], l_i[4], O[4][4];
    #pragma unroll
    for (int i = 0; i < 4; i++) {
        m_i[i] = -1e30f; l_i[i] = 0.f;
        #pragma unroll
        for (int j = 0; j < 4; j++) O[i][j] = 0.f;
    }

    for (int kb = 0; kb < 32; kb++) {
        int k0 = kb << 6;
        __syncthreads();
        #pragma unroll
        for (int j = 0; j < 4; j++) {
            int idx = (j << 8) + tid;
            int row = idx >> 4, c4 = (idx & 15) << 2;
            const float* kp = &g_qkv[base + (size_t)(k0 + row) * QKV3 + INNER + h * DHEAD + c4];
            float4 kv = *(const float4*)kp;
            KP[((c4 + 0) << 6) + row] = kv.x;
            KP[((c4 + 1) << 6) + row] = kv.y;
            KP[((c4 + 2) << 6) + row] = kv.z;
            KP[((c4 + 3) << 6) + row] = kv.w;
            *(float4*)&Vs[(row << 6) + c4] = *(const float4*)(kp + INNER);
        }
        float bf[4][4];
        #pragma unroll
        for (int i = 0; i < 4; i++)
            #pragma unroll
            for (int j = 0; j < 4; j++)
                bf[i][j] = __ldg(gb + k0 + j - i);
        __syncthreads();

        float acc[4][4];
        #pragma unroll
        for (int i = 0; i < 4; i++)
            #pragma unroll
            for (int j = 0; j < 4; j++) acc[i][j] = 0.f;
        #pragma unroll
        for (int d4 = 0; d4 < 64; d4 += 4) {
            float qv[4][4], kv[4][4];
            #pragma unroll
            for (int i = 0; i < 4; i++)
                *(float4*)qv[i] = *(const float4*)&Qs[(((ty << 2) + i) << 6) + d4];
            #pragma unroll
            for (int dd = 0; dd < 4; dd++)
                *(float4*)kv[dd] = *(const float4*)&KP[((d4 + dd) << 6) + (tx << 2)];
            #pragma unroll
            for (int i = 0; i < 4; i++)
                #pragma unroll
                for (int j = 0; j < 4; j++)
                    acc[i][j] += qv[i][0] * kv[0][j] + qv[i][1] * kv[1][j]
                               + qv[i][2] * kv[2][j] + qv[i][3] * kv[3][j];
        }
        #pragma unroll
        for (int i = 0; i < 4; i++)
            #pragma unroll
            for (int j = 0; j < 4; j++) acc[i][j] += bf[i][j];

        #pragma unroll
        for (int i = 0; i < 4; i++) {
            float rm = fmaxf(fmaxf(acc[i][0], acc[i][1]), fmaxf(acc[i][2], acc[i][3]));
            rm = fmaxf(rm, __shfl_xor_sync(0xffffffffu, rm, 8, 16));
            rm = fmaxf(rm, __shfl_xor_sync(0xffffffffu, rm, 4, 16));
            rm = fmaxf(rm, __shfl_xor_sync(0xffffffffu, rm, 2, 16));
            rm = fmaxf(rm, __shfl_xor_sync(0xffffffffu, rm, 1, 16));
            float newm  = fmaxf(m_i[i], rm);
            float scale = __expf(m_i[i] - newm);
            m_i[i] = newm;
            float rs = 0.f;
            #pragma unroll
            for (int j = 0; j < 4; j++) {
                acc[i][j] = __expf(acc[i][j] - newm);
                rs += acc[i][j];
            }
            rs += __shfl_xor_sync(0xffffffffu, rs, 8, 16);
            rs += __shfl_xor_sync(0xffffffffu, rs, 4, 16);
            rs += __shfl_xor_sync(0xffffffffu, rs, 2, 16);
            rs += __shfl_xor_sync(0xffffffffu, rs, 1, 16);
            l_i[i] = l_i[i] * scale + rs;
            #pragma unroll
            for (int j = 0; j < 4; j++) O[i][j] *= scale;
        }

        __syncthreads();
        #pragma unroll
        for (int i = 0; i < 4; i++)
            *(float4*)&KP[(((ty << 2) + i) << 6) + (tx << 2)] =
                make_float4(acc[i][0], acc[i][1], acc[i][2], acc[i][3]);
        __syncthreads();

        #pragma unroll
        for (int c4 = 0; c4 < 64; c4 += 4) {
            float pv[4][4], vv[4][4];
            #pragma unroll
            for (int i = 0; i < 4; i++)
                *(float4*)pv[i] = *(const float4*)&KP[(((ty << 2) + i) << 6) + c4];
            #pragma unroll
            for (int cc = 0; cc < 4; cc++)
                *(float4*)vv[cc] = *(const float4*)&Vs[((c4 + cc) << 6) + (tx << 2)];
            #pragma unroll
            for (int i = 0; i < 4; i++)
                #pragma unroll
                for (int j = 0; j < 4; j++)
                    O[i][j] += pv[i][0] * vv[0][j] + pv[i][1] * vv[1][j]
                             + pv[i][2] * vv[2][j] + pv[i][3] * vv[3][j];
        }
    }

    #pragma unroll
    for (int i = 0; i < 4; i++) {
        float inv = 1.f / l_i[i];
        int row = q0 + (ty << 2) + i;
        float4 o4 = make_float4(O[i][0] * inv, O[i][1] * inv, O[i][2] * inv, O[i][3] * inv);
        *(float4*)&g_ai[((size_t)b * SEQ + row) * INNER + h * DHEAD + (tx << 2)] = o4;
    }
}

// ---------------------------------------------------------------------------
extern "C" void kernel_launch(void* const* d_in, const int* in_sizes, int n_in,
                              void* d_out, int out_size)
{
    const float* hidden = (const float*)d_in[0];   // [2,2048,1024]
    const float* w_qkv  = (const float*)d_in[1];   // [1024,3072]
    const float* w_o    = (const float*)d_in[2];   // [1024,1024]
    const float* table  = (const float*)d_in[3];   // [32,16]
    float* out = (float*)d_out;

    float *qkv_ptr = nullptr, *ai_ptr = nullptr;
    cudaGetSymbolAddress((void**)&qkv_ptr, g_qkv);
    cudaGetSymbolAddress((void**)&ai_ptr,  g_ai);

    // 1) per-delta bias table
    bias_fill_kernel<<<16, 256>>>(table);

    // 2) position_bias output (second region of d_out)
    bias_write_kernel<<<dim3(SEQ, NHEADS), 512>>>(out + (size_t)BATCH * SEQ * DMODEL);

    // 3) QKV projection: [4096,1024] @ [1024,3072] (3xTF32 tensor cores)
    gemm_tf32x3_kernel<<<dim3(QKV3 / 128, (BATCH * SEQ) / 128), 256>>>(
        hidden, w_qkv, qkv_ptr, BATCH * SEQ, QKV3, DMODEL);

    // 4) fused attention
    attn_kernel<<<dim3(SEQ / 64, NHEADS, BATCH), 256>>>();

    // 5) output projection: [4096,1024] @ [1024,1024] -> first region of d_out
    gemm_tf32x3_kernel<<<dim3(DMODEL / 128, (BATCH * SEQ) / 128), 256>>>(
        ai_ptr, w_o, out, BATCH * SEQ, DMODEL, DMODEL);
}

// round 5
// speedup vs baseline: 1.7487x; 1.7487x over previous
#include <cuda_runtime.h>
#include <math.h>
#include <stdint.h>

#define BATCH   2
#define SEQ     2048
#define DMODEL  1024
#define NHEADS  16
#define DHEAD   64
#define INNER   1024        // NHEADS*DKV
#define QKV3    3072        // 3*INNER

// -------- scratch (device globals; no allocation allowed) --------
__device__ float g_qkv[(size_t)BATCH * SEQ * QKV3];   // 48 MB : [b*s][3072] (q|k|v)
__device__ float g_ai [(size_t)BATCH * SEQ * INNER];  // 16 MB : attention inner output
__device__ float g_bias[NHEADS * 4096];               // 256 KB: bias[h][ (k-q)+2048 ]

// ---------------------------------------------------------------------------
// 1) Fill per-delta bias table
// ---------------------------------------------------------------------------
__global__ void bias_fill_kernel(const float* __restrict__ table) {
    int idx = blockIdx.x * blockDim.x + threadIdx.x;  // 0..4095
    if (idx >= 4096) return;
    int rel = idx - 2048;                 // rel = k - q  (mem - ctx)
    int bucket = (rel > 0) ? 16 : 0;      // num_buckets//2 = 16
    int ad = rel < 0 ? -rel : rel;
    int bb;
    if (ad < 8) {
        bb = ad;
    } else {
        float rp = (float)ad;
        float l  = (float)log((double)(rp / 8.0f));     // correctly-rounded f32 log
        float v  = (l / 2.7725887f) * 8.0f;             // f32(log(16))
        bb = 8 + (int)v;
        if (bb > 15) bb = 15;
    }
    bucket += bb;
    #pragma unroll
    for (int h = 0; h < NHEADS; h++)
        g_bias[h * 4096 + idx] = table[bucket * NHEADS + h];
}

// ---------------------------------------------------------------------------
// 2) Write position_bias output [1,16,2048,2048]
// ---------------------------------------------------------------------------
__global__ void bias_write_kernel(float* __restrict__ out) {
    int q = blockIdx.x;
    int h = blockIdx.y;
    int k = threadIdx.x << 2;  // 512 threads * 4 = 2048
    const float* src = g_bias + h * 4096 + (2048 - q) + k;
    float4 v = make_float4(src[0], src[1], src[2], src[3]);
    *(float4*)(out + ((size_t)h * SEQ + q) * SEQ + k) = v;
}

// ---------------------------------------------------------------------------
// 3) Tensor-core GEMM: C[M,N] = A[M,K] @ B[K,N], 3xTF32 (fp32-quality)
//    128x128x8 tiles, double-buffered, 8 warps (2m x 4n), 64x32 warp tile
// ---------------------------------------------------------------------------
__device__ __forceinline__ void tf32_split(float x, uint32_t& hi, uint32_t& lo) {
    uint32_t h;
    asm("cvt.rna.tf32.f32 %0, %1;" : "=r"(h) : "f"(x));
    float r = x - __uint_as_float(h);
    uint32_t l;
    asm("cvt.rna.tf32.f32 %0, %1;" : "=r"(l) : "f"(r));
    hi = h; lo = l;
}

__device__ __forceinline__ void mma_tf32(float* d, const uint32_t* a, const uint32_t* b) {
    asm volatile(
        "mma.sync.aligned.m16n8k8.row.col.f32.tf32.tf32.f32 "
        "{%0,%1,%2,%3},{%4,%5,%6,%7},{%8,%9},{%0,%1,%2,%3};"
        : "+f"(d[0]), "+f"(d[1]), "+f"(d[2]), "+f"(d[3])
        : "r"(a[0]), "r"(a[1]), "r"(a[2]), "r"(a[3]), "r"(b[0]), "r"(b[1]));
}

#define AS_STRIDE 12    // 128 rows x (8 + pad) -> conflict-free A frag loads
#define BS_STRIDE 136   // 8 rows x (128 + pad) -> conflict-free B frag loads

__global__ __launch_bounds__(256) void gemm_tf32x3_kernel(
    const float* __restrict__ A, const float* __restrict__ B,
    float* __restrict__ C, int M, int N, int K)
{
    __shared__ float As[2][128 * AS_STRIDE];
    __shared__ float Bs[2][8 * BS_STRIDE];

    int tid  = threadIdx.x;
    int warp = tid >> 5, lane = tid & 31;
    int wm = warp & 1, wn = warp >> 1;     // 2 (m) x 4 (n)
    int bm = blockIdx.y << 7, bn = blockIdx.x << 7;

    // global load indices
    int ar = tid >> 1,  ac = (tid & 1) << 2;   // A tile: 128 x 8
    int br = tid >> 5,  bc = (tid & 31) << 2;  // B tile:   8 x 128
    const float* Ap = A + (size_t)(bm + ar) * K + ac;
    const float* Bp = B + (size_t)br * N + bn + bc;

    float acc[4][4][4];
    #pragma unroll
    for (int mi = 0; mi < 4; mi++)
        #pragma unroll
        for (int ni = 0; ni < 4; ni++)
            #pragma unroll
            for (int e = 0; e < 4; e++) acc[mi][ni][e] = 0.f;

    // preload first tile
    float4 a_v = *(const float4*)Ap;
    float4 b_v = *(const float4*)Bp;
    *(float4*)&As[0][ar * AS_STRIDE + ac] = a_v;
    *(float4*)&Bs[0][br * BS_STRIDE + bc] = b_v;
    __syncthreads();

    int frow = lane >> 2, fk = lane & 3;      // fragment row group / k index
    int buf = 0;

    for (int k0 = 8; k0 <= K; k0 += 8) {
        if (k0 < K) {
            a_v = *(const float4*)(Ap + k0);
            b_v = *(const float4*)(Bp + (size_t)k0 * N);
        }

        // ---- load + split fragments from smem buf ----
        uint32_t Ahi[4][4], Alo[4][4], Bhi[4][2], Blo[4][2];
        const float* as = As[buf];
        const float* bs = Bs[buf];
        #pragma unroll
        for (int mi = 0; mi < 4; mi++) {
            int r = (wm << 6) + (mi << 4) + frow;
            float a0 = as[r * AS_STRIDE + fk];
            float a1 = as[(r + 8) * AS_STRIDE + fk];
            float a2 = as[r * AS_STRIDE + fk + 4];
            float a3 = as[(r + 8) * AS_STRIDE + fk + 4];
            tf32_split(a0, Ahi[mi][0], Alo[mi][0]);
            tf32_split(a1, Ahi[mi][1], Alo[mi][1]);
            tf32_split(a2, Ahi[mi][2], Alo[mi][2]);
            tf32_split(a3, Ahi[mi][3], Alo[mi][3]);
        }
        #pragma unroll
        for (int ni = 0; ni < 4; ni++) {
            int n = (wn << 5) + (ni << 3) + frow;
            float b0 = bs[fk * BS_STRIDE + n];
            float b1 = bs[(fk + 4) * BS_STRIDE + n];
            tf32_split(b0, Bhi[ni][0], Blo[ni][0]);
            tf32_split(b1, Bhi[ni][1], Blo[ni][1]);
        }

        // ---- 3xTF32 MMAs ----
        #pragma unroll
        for (int mi = 0; mi < 4; mi++)
            #pragma unroll
            for (int ni = 0; ni < 4; ni++) {
                mma_tf32(acc[mi][ni], Ahi[mi], Blo[ni]);
                mma_tf32(acc[mi][ni], Alo[mi], Bhi[ni]);
                mma_tf32(acc[mi][ni], Ahi[mi], Bhi[ni]);
            }

        if (k0 < K) {
            *(float4*)&As[buf ^ 1][ar * AS_STRIDE + ac] = a_v;
            *(float4*)&Bs[buf ^ 1][br * BS_STRIDE + bc] = b_v;
        }
        __syncthreads();
        buf ^= 1;
    }

    // ---- epilogue ----
    #pragma unroll
    for (int mi = 0; mi < 4; mi++) {
        int r0 = bm + (wm << 6) + (mi << 4) + frow;
        #pragma unroll
        for (int ni = 0; ni < 4; ni++) {
            int c0 = bn + (wn << 5) + (ni << 3) + (fk << 1);
            *(float2*)&C[(size_t)r0 * N + c0]       = make_float2(acc[mi][ni][0], acc[mi][ni][1]);
            *(float2*)&C[(size_t)(r0 + 8) * N + c0] = make_float2(acc[mi][ni][2], acc[mi][ni][3]);
        }
    }
}

// ---------------------------------------------------------------------------
// 4) Flash attention (fp32), 64x64 tiles, 4x4 frags, bias from g_bias (L2)
//    K kept ROW-MAJOR with XOR swizzle (no transpose; conflict-free stores,
//    2-phase-optimal fragment reads). P overlays Ks after the S-loop.
//    grid: (32 q-tiles, 16 heads, 2 batch), 256 threads
// ---------------------------------------------------------------------------
__global__ __launch_bounds__(256, 2) void attn_kernel() {
    __shared__ float Qs[64 * 64];   // Q[row][d]
    __shared__ float Ks[64 * 64];   // K[row][d^sw] during S; then P[row][k] during PV
    __shared__ float Vs[64 * 64];   // V[k][d]

    int tid = threadIdx.x;
    int tx = tid & 15, ty = tid >> 4;
    int q0 = blockIdx.x << 6;
    int h  = blockIdx.y;
    int b  = blockIdx.z;
    size_t base = (size_t)b * SEQ * QKV3;

    const float* gb = g_bias + h * 4096 + 2048 - q0 + (tx << 2) - (ty << 2);

    #pragma unroll
    for (int j = 0; j < 4; j++) {
        int idx = (j << 8) + tid;
        int row = idx >> 4, c4 = (idx & 15) << 2;
        *(float4*)&Qs[(row << 6) + c4] =
            *(const float4*)&g_qkv[base + (size_t)(q0 + row) * QKV3 + h * DHEAD + c4];
    }

    float m_i[4], l_i[4], O[4][4];
    #pragma unroll
    for (int i = 0; i < 4; i++) {
        m_i[i] = -1e30f; l_i[i] = 0.f;
        #pragma unroll
        for (int j = 0; j < 4; j++) O[i][j] = 0.f;
    }

    for (int kb = 0; kb < 32; kb++) {
        int k0 = kb << 6;
        __syncthreads();   // previous PV finished reading Ks(P)/Vs
        // load K (row-major, XOR-swizzled columns) and V
        #pragma unroll
        for (int j = 0; j < 4; j++) {
            int idx = (j << 8) + tid;
            int row = idx >> 4, c4 = (idx & 15) << 2;
            const float* kp = &g_qkv[base + (size_t)(k0 + row) * QKV3 + INNER + h * DHEAD + c4];
            int sw = ((row >> 2) & 15) << 2;
            *(float4*)&Ks[(row << 6) + (c4 ^ sw)] = *(const float4*)kp;
            *(float4*)&Vs[(row << 6) + c4]        = *(const float4*)(kp + INNER);
        }
        // bias fragment (L2/L1-resident 256KB table); row i -> -i, col j -> +j
        float bf[4][4];
        #pragma unroll
        for (int i = 0; i < 4; i++)
            #pragma unroll
            for (int j = 0; j < 4; j++)
                bf[i][j] = __ldg(gb + k0 + j - i);
        __syncthreads();

        // S = Q K^T  (K fragments read row-major through the swizzle)
        float acc[4][4];
        #pragma unroll
        for (int i = 0; i < 4; i++)
            #pragma unroll
            for (int j = 0; j < 4; j++) acc[i][j] = 0.f;
        #pragma unroll
        for (int d4 = 0; d4 < 64; d4 += 4) {
            float qv[4][4], kv[4][4];
            #pragma unroll
            for (int i = 0; i < 4; i++)
                *(float4*)qv[i] = *(const float4*)&Qs[(((ty << 2) + i) << 6) + d4];
            int kc = d4 ^ (tx << 2);   // rows 4tx..4tx+3 share swizzle sw = tx<<2
            #pragma unroll
            for (int j = 0; j < 4; j++)
                *(float4*)kv[j] = *(const float4*)&Ks[(((tx << 2) + j) << 6) + kc];
            #pragma unroll
            for (int i = 0; i < 4; i++)
                #pragma unroll
                for (int j = 0; j < 4; j++)
                    acc[i][j] += qv[i][0] * kv[j][0] + qv[i][1] * kv[j][1]
                               + qv[i][2] * kv[j][2] + qv[i][3] * kv[j][3];
        }
        #pragma unroll
        for (int i = 0; i < 4; i++)
            #pragma unroll
            for (int j = 0; j < 4; j++) acc[i][j] += bf[i][j];

        // online softmax (row stats across the 16 tx lanes)
        #pragma unroll
        for (int i = 0; i < 4; i++) {
            float rm = fmaxf(fmaxf(acc[i][0], acc[i][1]), fmaxf(acc[i][2], acc[i][3]));
            rm = fmaxf(rm, __shfl_xor_sync(0xffffffffu, rm, 8, 16));
            rm = fmaxf(rm, __shfl_xor_sync(0xffffffffu, rm, 4, 16));
            rm = fmaxf(rm, __shfl_xor_sync(0xffffffffu, rm, 2, 16));
            rm = fmaxf(rm, __shfl_xor_sync(0xffffffffu, rm, 1, 16));
            float newm  = fmaxf(m_i[i], rm);
            float scale = __expf(m_i[i] - newm);
            m_i[i] = newm;
            float rs = 0.f;
            #pragma unroll
            for (int j = 0; j < 4; j++) {
                acc[i][j] = __expf(acc[i][j] - newm);
                rs += acc[i][j];
            }
            rs += __shfl_xor_sync(0xffffffffu, rs, 8, 16);
            rs += __shfl_xor_sync(0xffffffffu, rs, 4, 16);
            rs += __shfl_xor_sync(0xffffffffu, rs, 2, 16);
            rs += __shfl_xor_sync(0xffffffffu, rs, 1, 16);
            l_i[i] = l_i[i] * scale + rs;
            #pragma unroll
            for (int j = 0; j < 4; j++) O[i][j] *= scale;
        }

        __syncthreads();   // everyone done reading Ks (as K)
        #pragma unroll
        for (int i = 0; i < 4; i++)
            *(float4*)&Ks[(((ty << 2) + i) << 6) + (tx << 2)] =
                make_float4(acc[i][0], acc[i][1], acc[i][2], acc[i][3]);
        __syncthreads();

        // O += P @ V
        #pragma unroll
        for (int c4 = 0; c4 < 64; c4 += 4) {
            float pv[4][4], vv[4][4];
            #pragma unroll
            for (int i = 0; i < 4; i++)
                *(float4*)pv[i] = *(const float4*)&Ks[(((ty << 2) + i) << 6) + c4];
            #pragma unroll
            for (int cc = 0; cc < 4; cc++)
                *(float4*)vv[cc] = *(const float4*)&Vs[((c4 + cc) << 6) + (tx << 2)];
            #pragma unroll
            for (int i = 0; i < 4; i++)
                #pragma unroll
                for (int j = 0; j < 4; j++)
                    O[i][j] += pv[i][0] * vv[0][j] + pv[i][1] * vv[1][j]
                             + pv[i][2] * vv[2][j] + pv[i][3] * vv[3][j];
        }
    }

    // epilogue: normalize and store to g_ai[b][s][h*64+d]
    #pragma unroll
    for (int i = 0; i < 4; i++) {
        float inv = 1.f / l_i[i];
        int row = q0 + (ty << 2) + i;
        float4 o4 = make_float4(O[i][0] * inv, O[i][1] * inv, O[i][2] * inv, O[i][3] * inv);
        *(float4*)&g_ai[((size_t)b * SEQ + row) * INNER + h * DHEAD + (tx << 2)] = o4;
    }
}

// ---------------------------------------------------------------------------
extern "C" void kernel_launch(void* const* d_in, const int* in_sizes, int n_in,
                              void* d_out, int out_size)
{
    const float* hidden = (const float*)d_in[0];   // [2,2048,1024]
    const float* w_qkv  = (const float*)d_in[1];   // [1024,3072]
    const float* w_o    = (const float*)d_in[2];   // [1024,1024]
    const float* table  = (const float*)d_in[3];   // [32,16]
    float* out = (float*)d_out;

    float *qkv_ptr = nullptr, *ai_ptr = nullptr;
    cudaGetSymbolAddress((void**)&qkv_ptr, g_qkv);
    cudaGetSymbolAddress((void**)&ai_ptr,  g_ai);

    // 1) per-delta bias table
    bias_fill_kernel<<<16, 256>>>(table);

    // 2) position_bias output (second region of d_out)
    bias_write_kernel<<<dim3(SEQ, NHEADS), 512>>>(out + (size_t)BATCH * SEQ * DMODEL);

    // 3) QKV projection: [4096,1024] @ [1024,3072] (3xTF32 tensor cores)
    gemm_tf32x3_kernel<<<dim3(QKV3 / 128, (BATCH * SEQ) / 128), 256>>>(
        hidden, w_qkv, qkv_ptr, BATCH * SEQ, QKV3, DMODEL);

    // 4) fused attention
    attn_kernel<<<dim3(SEQ / 64, NHEADS, BATCH), 256>>>();

    // 5) output projection: [4096,1024] @ [1024,1024] -> first region of d_out
    gemm_tf32x3_kernel<<<dim3(DMODEL / 128, (BATCH * SEQ) / 128), 256>>>(
        ai_ptr, w_o, out, BATCH * SEQ, DMODEL, DMODEL);
}

// round 7
// speedup vs baseline: 2.5998x; 1.4867x over previous
#include <cuda_runtime.h>
#include <cuda_fp16.h>
#include <math.h>
#include <stdint.h>

#define BATCH   2
#define SEQ     2048
#define DMODEL  1024
#define NHEADS  16
#define DHEAD   64
#define INNER   1024
#define QKV3    3072
#define BH      (BATCH * NHEADS)

// -------- scratch (device globals; no allocation allowed) --------
__device__ float g_qkv[(size_t)BATCH * SEQ * QKV3];   // 48 MB
__device__ float g_ai [(size_t)BATCH * SEQ * INNER];  // 16 MB
__device__ float g_bias[NHEADS * 4096];               // 256 KB
// fp16 hi/lo splits for mma.sync attention
__device__ __half g_qh[(size_t)BH * SEQ * DHEAD];
__device__ __half g_ql[(size_t)BH * SEQ * DHEAD];
__device__ __half g_kh[(size_t)BH * SEQ * DHEAD];
__device__ __half g_kl[(size_t)BH * SEQ * DHEAD];
__device__ __half g_vth[(size_t)BH * DHEAD * SEQ];    // V^T [bh][d][s]
__device__ __half g_vtl[(size_t)BH * DHEAD * SEQ];

// ---------------------------------------------------------------------------
// 1) bias table
// ---------------------------------------------------------------------------
__global__ void bias_fill_kernel(const float* __restrict__ table) {
    int idx = blockIdx.x * blockDim.x + threadIdx.x;
    if (idx >= 4096) return;
    int rel = idx - 2048;
    int bucket = (rel > 0) ? 16 : 0;
    int ad = rel < 0 ? -rel : rel;
    int bb;
    if (ad < 8) {
        bb = ad;
    } else {
        float rp = (float)ad;
        float l  = (float)log((double)(rp / 8.0f));
        float v  = (l / 2.7725887f) * 8.0f;
        bb = 8 + (int)v;
        if (bb > 15) bb = 15;
    }
    bucket += bb;
    #pragma unroll
    for (int h = 0; h < NHEADS; h++)
        g_bias[h * 4096 + idx] = table[bucket * NHEADS + h];
}

// ---------------------------------------------------------------------------
// 2) position_bias output
// ---------------------------------------------------------------------------
__global__ void bias_write_kernel(float* __restrict__ out) {
    int q = blockIdx.x;
    int h = blockIdx.y;
    int k = threadIdx.x << 2;
    const float* src = g_bias + h * 4096 + (2048 - q) + k;
    float4 v = make_float4(src[0], src[1], src[2], src[3]);
    *(float4*)(out + ((size_t)h * SEQ + q) * SEQ + k) = v;
}

// ---------------------------------------------------------------------------
// 3) 3xTF32 GEMM (unchanged, proven)
// ---------------------------------------------------------------------------
__device__ __forceinline__ void tf32_split(float x, uint32_t& hi, uint32_t& lo) {
    uint32_t h;
    asm("cvt.rna.tf32.f32 %0, %1;" : "=r"(h) : "f"(x));
    float r = x - __uint_as_float(h);
    uint32_t l;
    asm("cvt.rna.tf32.f32 %0, %1;" : "=r"(l) : "f"(r));
    hi = h; lo = l;
}
__device__ __forceinline__ void mma_tf32(float* d, const uint32_t* a, const uint32_t* b) {
    asm volatile(
        "mma.sync.aligned.m16n8k8.row.col.f32.tf32.tf32.f32 "
        "{%0,%1,%2,%3},{%4,%5,%6,%7},{%8,%9},{%0,%1,%2,%3};"
        : "+f"(d[0]), "+f"(d[1]), "+f"(d[2]), "+f"(d[3])
        : "r"(a[0]), "r"(a[1]), "r"(a[2]), "r"(a[3]), "r"(b[0]), "r"(b[1]));
}
#define AS_STRIDE 12
#define BS_STRIDE 136

__global__ __launch_bounds__(256) void gemm_tf32x3_kernel(
    const float* __restrict__ A, const float* __restrict__ B,
    float* __restrict__ C, int M, int N, int K)
{
    __shared__ float As[2][128 * AS_STRIDE];
    __shared__ float Bs[2][8 * BS_STRIDE];
    int tid  = threadIdx.x;
    int warp = tid >> 5, lane = tid & 31;
    int wm = warp & 1, wn = warp >> 1;
    int bm = blockIdx.y << 7, bn = blockIdx.x << 7;
    int ar = tid >> 1,  ac = (tid & 1) << 2;
    int br = tid >> 5,  bc = (tid & 31) << 2;
    const float* Ap = A + (size_t)(bm + ar) * K + ac;
    const float* Bp = B + (size_t)br * N + bn + bc;

    float acc[4][4][4];
    #pragma unroll
    for (int mi = 0; mi < 4; mi++)
        #pragma unroll
        for (int ni = 0; ni < 4; ni++)
            #pragma unroll
            for (int e = 0; e < 4; e++) acc[mi][ni][e] = 0.f;

    float4 a_v = *(const float4*)Ap;
    float4 b_v = *(const float4*)Bp;
    *(float4*)&As[0][ar * AS_STRIDE + ac] = a_v;
    *(float4*)&Bs[0][br * BS_STRIDE + bc] = b_v;
    __syncthreads();

    int frow = lane >> 2, fk = lane & 3;
    int buf = 0;
    for (int k0 = 8; k0 <= K; k0 += 8) {
        if (k0 < K) {
            a_v = *(const float4*)(Ap + k0);
            b_v = *(const float4*)(Bp + (size_t)k0 * N);
        }
        uint32_t Ahi[4][4], Alo[4][4], Bhi[4][2], Blo[4][2];
        const float* as = As[buf];
        const float* bs = Bs[buf];
        #pragma unroll
        for (int mi = 0; mi < 4; mi++) {
            int r = (wm << 6) + (mi << 4) + frow;
            float a0 = as[r * AS_STRIDE + fk];
            float a1 = as[(r + 8) * AS_STRIDE + fk];
            float a2 = as[r * AS_STRIDE + fk + 4];
            float a3 = as[(r + 8) * AS_STRIDE + fk + 4];
            tf32_split(a0, Ahi[mi][0], Alo[mi][0]);
            tf32_split(a1, Ahi[mi][1], Alo[mi][1]);
            tf32_split(a2, Ahi[mi][2], Alo[mi][2]);
            tf32_split(a3, Ahi[mi][3], Alo[mi][3]);
        }
        #pragma unroll
        for (int ni = 0; ni < 4; ni++) {
            int n = (wn << 5) + (ni << 3) + frow;
            float b0 = bs[fk * BS_STRIDE + n];
            float b1 = bs[(fk + 4) * BS_STRIDE + n];
            tf32_split(b0, Bhi[ni][0], Blo[ni][0]);
            tf32_split(b1, Bhi[ni][1], Blo[ni][1]);
        }
        #pragma unroll
        for (int mi = 0; mi < 4; mi++)
            #pragma unroll
            for (int ni = 0; ni < 4; ni++) {
                mma_tf32(acc[mi][ni], Ahi[mi], Blo[ni]);
                mma_tf32(acc[mi][ni], Alo[mi], Bhi[ni]);
                mma_tf32(acc[mi][ni], Ahi[mi], Bhi[ni]);
            }
        if (k0 < K) {
            *(float4*)&As[buf ^ 1][ar * AS_STRIDE + ac] = a_v;
            *(float4*)&Bs[buf ^ 1][br * BS_STRIDE + bc] = b_v;
        }
        __syncthreads();
        buf ^= 1;
    }
    #pragma unroll
    for (int mi = 0; mi < 4; mi++) {
        int r0 = bm + (wm << 6) + (mi << 4) + frow;
        #pragma unroll
        for (int ni = 0; ni < 4; ni++) {
            int c0 = bn + (wn << 5) + (ni << 3) + (fk << 1);
            *(float2*)&C[(size_t)r0 * N + c0]       = make_float2(acc[mi][ni][0], acc[mi][ni][1]);
            *(float2*)&C[(size_t)(r0 + 8) * N + c0] = make_float2(acc[mi][ni][2], acc[mi][ni][3]);
        }
    }
}

// ---------------------------------------------------------------------------
// 4) Prep: split Q,K into fp16 hi/lo [bh][s][64]; V into transposed hi/lo
//    [bh][d][s]. grid (32, 16, 2) x 256
// ---------------------------------------------------------------------------
__device__ __forceinline__ uint32_t packh2(float lo, float hi) {
    __half2 p = __halves2half2(__float2half_rn(lo), __float2half_rn(hi));
    return *(uint32_t*)&p;
}

__global__ __launch_bounds__(256) void prep_kernel() {
    __shared__ __half vh_s[64][68], vl_s[64][68];
    int tid = threadIdx.x;
    int st = blockIdx.x, h = blockIdx.y, b = blockIdx.z;
    int s0 = st << 6;
    int bh = b * NHEADS + h;

    #pragma unroll
    for (int j = 0; j < 4; j++) {
        int i = tid + (j << 8);
        int row = i >> 4, d4 = (i & 15) << 2;
        const float* base = g_qkv + (size_t)(b * SEQ + s0 + row) * QKV3 + h * DHEAD + d4;
        float4 qv = *(const float4*)base;
        float4 kv = *(const float4*)(base + INNER);
        float4 vv = *(const float4*)(base + 2 * INNER);
        size_t dst = (size_t)(bh * SEQ + s0 + row) * DHEAD + d4;
        // Q hi/lo
        float q0h = __half2float(__float2half_rn(qv.x));
        float q1h = __half2float(__float2half_rn(qv.y));
        float q2h = __half2float(__float2half_rn(qv.z));
        float q3h = __half2float(__float2half_rn(qv.w));
        *(uint2*)(g_qh + dst) = make_uint2(packh2(qv.x, qv.y), packh2(qv.z, qv.w));
        *(uint2*)(g_ql + dst) = make_uint2(packh2(qv.x - q0h, qv.y - q1h), packh2(qv.z - q2h, qv.w - q3h));
        // K hi/lo
        float k0h = __half2float(__float2half_rn(kv.x));
        float k1h = __half2float(__float2half_rn(kv.y));
        float k2h = __half2float(__float2half_rn(kv.z));
        float k3h = __half2float(__float2half_rn(kv.w));
        *(uint2*)(g_kh + dst) = make_uint2(packh2(kv.x, kv.y), packh2(kv.z, kv.w));
        *(uint2*)(g_kl + dst) = make_uint2(packh2(kv.x - k0h, kv.y - k1h), packh2(kv.z - k2h, kv.w - k3h));
        // V -> smem (transpose staging)
        float v0h = __half2float(__float2half_rn(vv.x));
        float v1h = __half2float(__float2half_rn(vv.y));
        float v2h = __half2float(__float2half_rn(vv.z));
        float v3h = __half2float(__float2half_rn(vv.w));
        vh_s[row][d4 + 0] = __float2half_rn(vv.x);
        vh_s[row][d4 + 1] = __float2half_rn(vv.y);
        vh_s[row][d4 + 2] = __float2half_rn(vv.z);
        vh_s[row][d4 + 3] = __float2half_rn(vv.w);
        vl_s[row][d4 + 0] = __float2half_rn(vv.x - v0h);
        vl_s[row][d4 + 1] = __float2half_rn(vv.y - v1h);
        vl_s[row][d4 + 2] = __float2half_rn(vv.z - v2h);
        vl_s[row][d4 + 3] = __float2half_rn(vv.w - v3h);
    }
    __syncthreads();
    #pragma unroll
    for (int j = 0; j < 4; j++) {
        int i = tid + (j << 8);
        int drow = i >> 4, s4 = (i & 15) << 2;
        size_t dst = (size_t)(bh * DHEAD + drow) * SEQ + s0 + s4;
        __half2 h0 = __halves2half2(vh_s[s4 + 0][drow], vh_s[s4 + 1][drow]);
        __half2 h1 = __halves2half2(vh_s[s4 + 2][drow], vh_s[s4 + 3][drow]);
        *(uint2*)(g_vth + dst) = make_uint2(*(uint32_t*)&h0, *(uint32_t*)&h1);
        __half2 l0 = __halves2half2(vl_s[s4 + 0][drow], vl_s[s4 + 1][drow]);
        __half2 l1 = __halves2half2(vl_s[s4 + 2][drow], vl_s[s4 + 3][drow]);
        *(uint2*)(g_vtl + dst) = make_uint2(*(uint32_t*)&l0, *(uint32_t*)&l1);
    }
}

// ---------------------------------------------------------------------------
// 5) mma.sync fp16 flash attention. grid (16, 16, 2) x 256 threads.
//    8 warps x 16 q-rows = 128-row q-tile; 64-key tiles; fp16 hi/lo x3 comp.
// ---------------------------------------------------------------------------
__device__ __forceinline__ uint32_t smem_u32(const void* p) {
    uint32_t a;
    asm("{ .reg .u64 t; cvta.to.shared.u64 t, %1; cvt.u32.u64 %0, t; }" : "=r"(a) : "l"(p));
    return a;
}
__device__ __forceinline__ void ldsm4(uint32_t* r, uint32_t a) {
    asm volatile("ldmatrix.sync.aligned.m8n8.x4.shared.b16 {%0,%1,%2,%3}, [%4];"
        : "=r"(r[0]), "=r"(r[1]), "=r"(r[2]), "=r"(r[3]) : "r"(a));
}
__device__ __forceinline__ void mma_fp16(float* d, const uint32_t* a, const uint32_t* b) {
    asm volatile("mma.sync.aligned.m16n8k16.row.col.f32.f16.f16.f32 "
        "{%0,%1,%2,%3},{%4,%5,%6,%7},{%8,%9},{%0,%1,%2,%3};"
        : "+f"(d[0]), "+f"(d[1]), "+f"(d[2]), "+f"(d[3])
        : "r"(a[0]), "r"(a[1]), "r"(a[2]), "r"(a[3]), "r"(b[0]), "r"(b[1]));
}
// fast exp on the FMA pipe (no MUFU): exp(x) = 2^(x*log2e), deg-4 poly
__device__ __forceinline__ float fexp(float x) {
    x = fmaxf(x, -87.0f);
    float t  = x * 1.4426950408889634f;
    float fn = t + 12582912.0f;                        // round-to-nearest magic
    int   ni = __float_as_int(fn) - 0x4B400000;
    float f  = t - (fn - 12582912.0f);
    float p  = 9.6784e-3f;
    p = fmaf(p, f, 5.550411e-2f);
    p = fmaf(p, f, 2.4022651e-1f);
    p = fmaf(p, f, 6.9314718e-1f);
    p = fmaf(p, f, 1.0f);
    return __int_as_float(__float_as_int(p) + (ni << 23));
}

#define SM_QH 0          // 16 KB (128 x 64 fp16)
#define SM_QL 16384
#define SM_KH 32768      // 8 KB (64 x 64 fp16)
#define SM_KL 40960
#define SM_VH 49152
#define SM_VL 57344
#define SM_TOT 65536

// 64x64 fp16 tile -> XOR-swizzled smem (rows 128B; chunk ^= row&7)
__device__ __forceinline__ void ld_tile64h(char* dst, const __half* src,
                                           int rstride, int tid) {
    #pragma unroll
    for (int j = 0; j < 2; j++) {
        int i = tid + (j << 8);
        int row = i >> 3, ch = i & 7;
        int off = (row << 7) + ((ch ^ (row & 7)) << 4);
        *(uint4*)(dst + off) = *(const uint4*)(src + (size_t)row * rstride + (ch << 3));
    }
}

__global__ __launch_bounds__(256) void attn_mma_kernel() {
    extern __shared__ char sm[];
    uint32_t sb = smem_u32(sm);
    int tid = threadIdx.x, warp = tid >> 5, lane = tid & 31;
    int qt = blockIdx.x, h = blockIdx.y, b = blockIdx.z;
    int q0 = qt << 7, bh = b * NHEADS + h;

    // load Q tiles (hi/lo), swizzled
    {
        const __half* qh = g_qh + (size_t)(bh * SEQ + q0) * DHEAD;
        const __half* ql = g_ql + (size_t)(bh * SEQ + q0) * DHEAD;
        #pragma unroll
        for (int j = 0; j < 4; j++) {
            int i = tid + (j << 8);
            int row = i >> 3, ch = i & 7;
            int off = (row << 7) + ((ch ^ (row & 7)) << 4);
            *(uint4*)(sm + SM_QH + off) = *(const uint4*)(qh + (size_t)row * DHEAD + (ch << 3));
            *(uint4*)(sm + SM_QL + off) = *(const uint4*)(ql + (size_t)row * DHEAD + (ch << 3));
        }
    }

    int g = lane >> 2, tg = lane & 3;
    int rw = warp << 4;
    int r0 = rw + g;                         // local q-row (r1 = r0+8)
    // A-frag ldmatrix lane addressing (rows rw..rw+15)
    int arow = rw + (lane & 7) + (((lane >> 3) & 1) << 3);
    int ach  = (lane >> 4);                  // +0/+1 chunk within kstep
    int asw  = arow & 7;
    uint32_t abase = (uint32_t)(arow << 7);
    // B-frag ldmatrix lane addressing (rows within 16-row pair block)
    int brlo = (lane & 7) + ((lane >> 4) << 3);
    int bch  = (lane >> 3) & 1;

    const float* gb2 = g_bias + h * 4096 + 2048 - q0;  // idx: k0 + c - r
    float O[8][4];
    #pragma unroll
    for (int nd = 0; nd < 8; nd++)
        #pragma unroll
        for (int e = 0; e < 4; e++) O[nd][e] = 0.f;
    float m0r = -1e30f, m1r = -1e30f, l0 = 0.f, l1 = 0.f;

    for (int kb = 0; kb < 32; kb++) {
        int k0 = kb << 6;
        __syncthreads();
        ld_tile64h(sm + SM_KH, g_kh + (size_t)(bh * SEQ + k0) * DHEAD, DHEAD, tid);
        ld_tile64h(sm + SM_KL, g_kl + (size_t)(bh * SEQ + k0) * DHEAD, DHEAD, tid);
        ld_tile64h(sm + SM_VH, g_vth + (size_t)bh * DHEAD * SEQ + k0, SEQ, tid);
        ld_tile64h(sm + SM_VL, g_vtl + (size_t)bh * DHEAD * SEQ + k0, SEQ, tid);
        __syncthreads();

        // ---- S = Q K^T (fp16 x3) ----
        float S[8][4];
        #pragma unroll
        for (int nt = 0; nt < 8; nt++)
            #pragma unroll
            for (int e = 0; e < 4; e++) S[nt][e] = 0.f;

        #pragma unroll
        for (int ks = 0; ks < 4; ks++) {
            uint32_t qhf[4], qlf[4];
            uint32_t aoff = abase + ((((ks << 1) + ach) ^ asw) << 4);
            ldsm4(qhf, sb + SM_QH + aoff);
            ldsm4(qlf, sb + SM_QL + aoff);
            #pragma unroll
            for (int np = 0; np < 4; np++) {
                int brow = (np << 4) + brlo;
                uint32_t boff = (uint32_t)(brow << 7) + ((((ks << 1) + bch) ^ (brow & 7)) << 4);
                uint32_t kh4[4], kl4[4];
                ldsm4(kh4, sb + SM_KH + boff);
                ldsm4(kl4, sb + SM_KL + boff);
                mma_fp16(S[2 * np],     qhf, kh4);
                mma_fp16(S[2 * np],     qlf, kh4);
                mma_fp16(S[2 * np],     qhf, kl4);
                mma_fp16(S[2 * np + 1], qhf, kh4 + 2);
                mma_fp16(S[2 * np + 1], qlf, kh4 + 2);
                mma_fp16(S[2 * np + 1], qhf, kl4 + 2);
            }
        }

        // ---- bias + online softmax ----
        float ml0 = -1e30f, ml1 = -1e30f;
        #pragma unroll
        for (int nt = 0; nt < 8; nt++) {
            int c = k0 + (nt << 3) + (tg << 1);
            S[nt][0] += __ldg(gb2 + c - r0);
            S[nt][1] += __ldg(gb2 + c + 1 - r0);
            S[nt][2] += __ldg(gb2 + c - r0 - 8);
            S[nt][3] += __ldg(gb2 + c + 1 - r0 - 8);
            ml0 = fmaxf(ml0, fmaxf(S[nt][0], S[nt][1]));
            ml1 = fmaxf(ml1, fmaxf(S[nt][2], S[nt][3]));
        }
        ml0 = fmaxf(ml0, __shfl_xor_sync(0xffffffffu, ml0, 1));
        ml0 = fmaxf(ml0, __shfl_xor_sync(0xffffffffu, ml0, 2));
        ml1 = fmaxf(ml1, __shfl_xor_sync(0xffffffffu, ml1, 1));
        ml1 = fmaxf(ml1, __shfl_xor_sync(0xffffffffu, ml1, 2));
        float mn0 = fmaxf(m0r, ml0), mn1 = fmaxf(m1r, ml1);
        float sc0 = fexp(m0r - mn0), sc1 = fexp(m1r - mn1);
        m0r = mn0; m1r = mn1;
        float rs0 = 0.f, rs1 = 0.f;
        #pragma unroll
        for (int nt = 0; nt < 8; nt++) {
            S[nt][0] = fexp(S[nt][0] - mn0);
            S[nt][1] = fexp(S[nt][1] - mn0);
            S[nt][2] = fexp(S[nt][2] - mn1);
            S[nt][3] = fexp(S[nt][3] - mn1);
            rs0 += S[nt][0] + S[nt][1];
            rs1 += S[nt][2] + S[nt][3];
        }
        l0 = l0 * sc0 + rs0;
        l1 = l1 * sc1 + rs1;
        #pragma unroll
        for (int nd = 0; nd < 8; nd++) {
            O[nd][0] *= sc0; O[nd][1] *= sc0;
            O[nd][2] *= sc1; O[nd][3] *= sc1;
        }

        // ---- P -> fp16 hi/lo A-frags (register reuse; no smem) ----
        uint32_t Ph[4][4], Pl[4][4];
        #pragma unroll
        for (int j = 0; j < 4; j++) {
            #pragma unroll
            for (int e = 0; e < 2; e++) {         // e=0: nt=2j, e=1: nt=2j+1
                int nt = 2 * j + e;
                float a0 = S[nt][0], a1 = S[nt][1], a2 = S[nt][2], a3 = S[nt][3];
                float h0 = __half2float(__float2half_rn(a0));
                float h1 = __half2float(__float2half_rn(a1));
                float h2 = __half2float(__float2half_rn(a2));
                float h3 = __half2float(__float2half_rn(a3));
                Ph[j][2 * e + 0] = packh2(a0, a1);
                Ph[j][2 * e + 1] = packh2(a2, a3);
                Pl[j][2 * e + 0] = packh2(a0 - h0, a1 - h1);
                Pl[j][2 * e + 1] = packh2(a2 - h2, a3 - h3);
            }
        }

        // ---- O += P V (fp16 x3) ----
        #pragma unroll
        for (int ks = 0; ks < 4; ks++) {
            #pragma unroll
            for (int np = 0; np < 4; np++) {
                int brow = (np << 4) + brlo;
                uint32_t boff = (uint32_t)(brow << 7) + ((((ks << 1) + bch) ^ (brow & 7)) << 4);
                uint32_t vh4[4], vl4[4];
                ldsm4(vh4, sb + SM_VH + boff);
                ldsm4(vl4, sb + SM_VL + boff);
                mma_fp16(O[2 * np],     Ph[ks], vh4);
                mma_fp16(O[2 * np],     Pl[ks], vh4);
                mma_fp16(O[2 * np],     Ph[ks], vl4);
                mma_fp16(O[2 * np + 1], Ph[ks], vh4 + 2);
                mma_fp16(O[2 * np + 1], Pl[ks], vh4 + 2);
                mma_fp16(O[2 * np + 1], Ph[ks], vl4 + 2);
            }
        }
    }

    // ---- epilogue ----
    l0 += __shfl_xor_sync(0xffffffffu, l0, 1);
    l0 += __shfl_xor_sync(0xffffffffu, l0, 2);
    l1 += __shfl_xor_sync(0xffffffffu, l1, 1);
    l1 += __shfl_xor_sync(0xffffffffu, l1, 2);
    float i0 = 1.f / l0, i1 = 1.f / l1;
    float* op0 = g_ai + ((size_t)b * SEQ + q0 + r0) * INNER + h * DHEAD + (tg << 1);
    float* op1 = op0 + 8 * INNER;
    #pragma unroll
    for (int nd = 0; nd < 8; nd++) {
        *(float2*)(op0 + (nd << 3)) = make_float2(O[nd][0] * i0, O[nd][1] * i0);
        *(float2*)(op1 + (nd << 3)) = make_float2(O[nd][2] * i1, O[nd][3] * i1);
    }
}

// ---------------------------------------------------------------------------
extern "C" void kernel_launch(void* const* d_in, const int* in_sizes, int n_in,
                              void* d_out, int out_size)
{
    const float* hidden = (const float*)d_in[0];
    const float* w_qkv  = (const float*)d_in[1];
    const float* w_o    = (const float*)d_in[2];
    const float* table  = (const float*)d_in[3];
    float* out = (float*)d_out;

    float *qkv_ptr = nullptr, *ai_ptr = nullptr;
    cudaGetSymbolAddress((void**)&qkv_ptr, g_qkv);
    cudaGetSymbolAddress((void**)&ai_ptr,  g_ai);

    cudaFuncSetAttribute(attn_mma_kernel,
                         cudaFuncAttributeMaxDynamicSharedMemorySize, SM_TOT);

    bias_fill_kernel<<<16, 256>>>(table);
    bias_write_kernel<<<dim3(SEQ, NHEADS), 512>>>(out + (size_t)BATCH * SEQ * DMODEL);
    gemm_tf32x3_kernel<<<dim3(QKV3 / 128, (BATCH * SEQ) / 128), 256>>>(
        hidden, w_qkv, qkv_ptr, BATCH * SEQ, QKV3, DMODEL);
    prep_kernel<<<dim3(32, NHEADS, BATCH), 256>>>();
    attn_mma_kernel<<<dim3(16, NHEADS, BATCH), 256, SM_TOT>>>();
    gemm_tf32x3_kernel<<<dim3(DMODEL / 128, (BATCH * SEQ) / 128), 256>>>(
        ai_ptr, w_o, out, BATCH * SEQ, DMODEL, DMODEL);
}

// round 11
// speedup vs baseline: 3.9065x; 1.5026x over previous
#include <cuda_runtime.h>
#include <cuda_fp16.h>
#include <math.h>
#include <stdint.h>

#define BATCH   2
#define SEQ     2048
#define DMODEL  1024
#define NHEADS  16
#define DHEAD   64
#define INNER   1024
#define QKV3    3072
#define BH      (BATCH * NHEADS)

// -------- scratch (device globals; no allocation allowed) --------
__device__ float g_qkv[(size_t)BATCH * SEQ * QKV3];   // 48 MB
__device__ float g_bias[NHEADS * 4096];               // 256 KB
// fp16 hi/lo splits
__device__ __half g_qh[(size_t)BH * SEQ * DHEAD];
__device__ __half g_ql[(size_t)BH * SEQ * DHEAD];
__device__ __half g_kh[(size_t)BH * SEQ * DHEAD];
__device__ __half g_kl[(size_t)BH * SEQ * DHEAD];
__device__ __half g_vth[(size_t)BH * DHEAD * SEQ];    // V^T [bh][d][s]
__device__ __half g_vtl[(size_t)BH * DHEAD * SEQ];
__device__ __half g_hh[(size_t)BATCH * SEQ * DMODEL]; // hidden split
__device__ __half g_hl[(size_t)BATCH * SEQ * DMODEL];
__device__ __half g_wqh[(size_t)QKV3 * DMODEL];       // w_qkv^T split [3072][1024]
__device__ __half g_wql[(size_t)QKV3 * DMODEL];
__device__ __half g_woh[(size_t)DMODEL * INNER];      // w_o^T split [1024][1024]
__device__ __half g_wol[(size_t)DMODEL * INNER];
__device__ __half g_aih[(size_t)BATCH * SEQ * INNER]; // attention out split
__device__ __half g_ail[(size_t)BATCH * SEQ * INNER];

__device__ __forceinline__ uint32_t smem_u32(const void* p) {
    uint32_t a;
    asm("{ .reg .u64 t; cvta.to.shared.u64 t, %1; cvt.u32.u64 %0, t; }" : "=r"(a) : "l"(p));
    return a;
}
__device__ __forceinline__ uint32_t packh2(float lo, float hi) {
    __half2 p = __halves2half2(__float2half_rn(lo), __float2half_rn(hi));
    return *(uint32_t*)&p;
}
__device__ __forceinline__ void ldsm4(uint32_t* r, uint32_t a) {
    asm volatile("ldmatrix.sync.aligned.m8n8.x4.shared.b16 {%0,%1,%2,%3}, [%4];"
        : "=r"(r[0]), "=r"(r[1]), "=r"(r[2]), "=r"(r[3]) : "r"(a));
}
__device__ __forceinline__ void mma_fp16(float* d, const uint32_t* a, const uint32_t* b) {
    asm volatile("mma.sync.aligned.m16n8k16.row.col.f32.f16.f16.f32 "
        "{%0,%1,%2,%3},{%4,%5,%6,%7},{%8,%9},{%0,%1,%2,%3};"
        : "+f"(d[0]), "+f"(d[1]), "+f"(d[2]), "+f"(d[3])
        : "r"(a[0]), "r"(a[1]), "r"(a[2]), "r"(a[3]), "r"(b[0]), "r"(b[1]));
}
// FMA-pipe exp (no MUFU)
__device__ __forceinline__ float fexp(float x) {
    x = fmaxf(x, -87.0f);
    float t  = x * 1.4426950408889634f;
    float fn = t + 12582912.0f;
    int   ni = __float_as_int(fn) - 0x4B400000;
    float f  = t - (fn - 12582912.0f);
    float p  = 9.6784e-3f;
    p = fmaf(p, f, 5.550411e-2f);
    p = fmaf(p, f, 2.4022651e-1f);
    p = fmaf(p, f, 6.9314718e-1f);
    p = fmaf(p, f, 1.0f);
    return __int_as_float(__float_as_int(p) + (ni << 23));
}

// ---------------------------------------------------------------------------
// 1) bias table
// ---------------------------------------------------------------------------
__global__ void bias_fill_kernel(const float* __restrict__ table) {
    int idx = blockIdx.x * blockDim.x + threadIdx.x;
    if (idx >= 4096) return;
    int rel = idx - 2048;
    int bucket = (rel > 0) ? 16 : 0;
    int ad = rel < 0 ? -rel : rel;
    int bb;
    if (ad < 8) {
        bb = ad;
    } else {
        float rp = (float)ad;
        float l  = (float)log((double)(rp / 8.0f));
        float v  = (l / 2.7725887f) * 8.0f;
        bb = 8 + (int)v;
        if (bb > 15) bb = 15;
    }
    bucket += bb;
    #pragma unroll
    for (int h = 0; h < NHEADS; h++)
        g_bias[h * 4096 + idx] = table[bucket * NHEADS + h];
}

// ---------------------------------------------------------------------------
// 2) position_bias output
// ---------------------------------------------------------------------------
__global__ void bias_write_kernel(float* __restrict__ out) {
    int q = blockIdx.x;
    int h = blockIdx.y;
    int k = threadIdx.x << 2;
    const float* src = g_bias + h * 4096 + (2048 - q) + k;
    float4 v = make_float4(src[0], src[1], src[2], src[3]);
    *(float4*)(out + ((size_t)h * SEQ + q) * SEQ + k) = v;
}

// ---------------------------------------------------------------------------
// 3a) hidden split: fp32 -> fp16 hi/lo
// ---------------------------------------------------------------------------
__global__ __launch_bounds__(256) void hsplit_kernel(const float* __restrict__ src) {
    size_t i = ((size_t)blockIdx.x * 256 + threadIdx.x) << 2;
    float4 v = *(const float4*)(src + i);
    float h0 = __half2float(__float2half_rn(v.x));
    float h1 = __half2float(__float2half_rn(v.y));
    float h2 = __half2float(__float2half_rn(v.z));
    float h3 = __half2float(__float2half_rn(v.w));
    *(uint2*)(g_hh + i) = make_uint2(packh2(v.x, v.y), packh2(v.z, v.w));
    *(uint2*)(g_hl + i) = make_uint2(packh2(v.x - h0, v.y - h1), packh2(v.z - h2, v.w - h3));
}

// ---------------------------------------------------------------------------
// 3b) weight transpose + split: w[K=1024][N] -> out[N][1024] fp16 hi/lo
//     grid (N/64, 16), 256 threads
// ---------------------------------------------------------------------------
__global__ __launch_bounds__(256) void wsplit_kernel(
    const float* __restrict__ w, __half* __restrict__ outh,
    __half* __restrict__ outl, int N)
{
    __shared__ float st[64][68];
    int tid = threadIdx.x;
    int n0 = blockIdx.x << 6, k0 = blockIdx.y << 6;
    #pragma unroll
    for (int j = 0; j < 4; j++) {
        int i = tid + (j << 8);
        int kr = i >> 4, nc = (i & 15) << 2;
        float4 v = *(const float4*)(w + (size_t)(k0 + kr) * N + n0 + nc);
        st[nc + 0][kr] = v.x;
        st[nc + 1][kr] = v.y;
        st[nc + 2][kr] = v.z;
        st[nc + 3][kr] = v.w;
    }
    __syncthreads();
    #pragma unroll
    for (int j = 0; j < 4; j++) {
        int i = tid + (j << 8);
        int nr = i >> 4, kc = (i & 15) << 2;
        float a = st[nr][kc], b = st[nr][kc + 1], c = st[nr][kc + 2], d = st[nr][kc + 3];
        float ha = __half2float(__float2half_rn(a));
        float hb = __half2float(__float2half_rn(b));
        float hc = __half2float(__float2half_rn(c));
        float hd = __half2float(__float2half_rn(d));
        size_t dst = (size_t)(n0 + nr) * DMODEL + k0 + kc;
        *(uint2*)(outh + dst) = make_uint2(packh2(a, b), packh2(c, d));
        *(uint2*)(outl + dst) = make_uint2(packh2(a - ha, b - hb), packh2(c - hc, d - hd));
    }
}

// ---------------------------------------------------------------------------
// 4) fp16x3 GEMM: C[M,N] = A @ B^T, A=[M][K] h/l, Bt=[N][K] h/l, K=1024
//    CTA tile 128m x 64n, K-chunk 64; 8 warps (4m x 2n), warp tile 32x32
// ---------------------------------------------------------------------------
#define GS_AH 0
#define GS_AL 16384
#define GS_BH 32768
#define GS_BL 40960
#define GS_TOT 49152

__global__ __launch_bounds__(256) void gemm_fp16x3_kernel(
    const __half* __restrict__ Ah, const __half* __restrict__ Al,
    const __half* __restrict__ Bh, const __half* __restrict__ Bl,
    float* __restrict__ C, int N, int K)
{
    extern __shared__ char sm[];
    uint32_t sb = smem_u32(sm);
    int tid = threadIdx.x, warp = tid >> 5, lane = tid & 31;
    int bn = blockIdx.x << 6, bm = blockIdx.y << 7;
    int wm = warp >> 1, wn = warp & 1;

    int arow_l = (lane & 15), ach = lane >> 4;
    int brlo = (lane & 7) + ((lane >> 4) << 3), bch = (lane >> 3) & 1;
    int g = lane >> 2, tg = lane & 3;

    float acc[2][4][4];
    #pragma unroll
    for (int mi = 0; mi < 2; mi++)
        #pragma unroll
        for (int nb = 0; nb < 4; nb++)
            #pragma unroll
            for (int e = 0; e < 4; e++) acc[mi][nb][e] = 0.f;

    for (int k0 = 0; k0 < K; k0 += 64) {
        __syncthreads();
        // stage A (128 rows x 64k), swizzled
        #pragma unroll
        for (int j = 0; j < 4; j++) {
            int i = tid + (j << 8);
            int row = i >> 3, ch = i & 7;
            int off = (row << 7) + ((ch ^ (row & 7)) << 4);
            *(uint4*)(sm + GS_AH + off) = *(const uint4*)(Ah + (size_t)(bm + row) * K + k0 + (ch << 3));
            *(uint4*)(sm + GS_AL + off) = *(const uint4*)(Al + (size_t)(bm + row) * K + k0 + (ch << 3));
        }
        // stage B (64 rows x 64k)
        #pragma unroll
        for (int j = 0; j < 2; j++) {
            int i = tid + (j << 8);
            int row = i >> 3, ch = i & 7;
            int off = (row << 7) + ((ch ^ (row & 7)) << 4);
            *(uint4*)(sm + GS_BH + off) = *(const uint4*)(Bh + (size_t)(bn + row) * K + k0 + (ch << 3));
            *(uint4*)(sm + GS_BL + off) = *(const uint4*)(Bl + (size_t)(bn + row) * K + k0 + (ch << 3));
        }
        __syncthreads();

        #pragma unroll
        for (int ks = 0; ks < 4; ks++) {
            uint32_t ah[2][4], al[2][4], bh4[2][4], bl4[2][4];
            #pragma unroll
            for (int mi = 0; mi < 2; mi++) {
                int arow = (wm << 5) + (mi << 4) + arow_l;
                uint32_t aoff = (uint32_t)(arow << 7) + ((((ks << 1) + ach) ^ (arow & 7)) << 4);
                ldsm4(ah[mi], sb + GS_AH + aoff);
                ldsm4(al[mi], sb + GS_AL + aoff);
            }
            #pragma unroll
            for (int np = 0; np < 2; np++) {
                int brow = (wn << 5) + (np << 4) + brlo;
                uint32_t boff = (uint32_t)(brow << 7) + ((((ks << 1) + bch) ^ (brow & 7)) << 4);
                ldsm4(bh4[np], sb + GS_BH + boff);
                ldsm4(bl4[np], sb + GS_BL + boff);
            }
            #pragma unroll
            for (int mi = 0; mi < 2; mi++)
                #pragma unroll
                for (int np = 0; np < 2; np++) {
                    mma_fp16(acc[mi][2 * np],     ah[mi], bh4[np]);
                    mma_fp16(acc[mi][2 * np],     al[mi], bh4[np]);
                    mma_fp16(acc[mi][2 * np],     ah[mi], bl4[np]);
                    mma_fp16(acc[mi][2 * np + 1], ah[mi], bh4[np] + 2);
                    mma_fp16(acc[mi][2 * np + 1], al[mi], bh4[np] + 2);
                    mma_fp16(acc[mi][2 * np + 1], ah[mi], bl4[np] + 2);
                }
        }
    }

    #pragma unroll
    for (int mi = 0; mi < 2; mi++) {
        int r = bm + (wm << 5) + (mi << 4) + g;
        #pragma unroll
        for (int nb = 0; nb < 4; nb++) {
            int c = bn + (wn << 5) + (nb << 3) + (tg << 1);
            *(float2*)&C[(size_t)r * N + c]       = make_float2(acc[mi][nb][0], acc[mi][nb][1]);
            *(float2*)&C[(size_t)(r + 8) * N + c] = make_float2(acc[mi][nb][2], acc[mi][nb][3]);
        }
    }
}

// ---------------------------------------------------------------------------
// 5) Prep: split Q,K fp16 hi/lo; V transposed hi/lo. grid (32,16,2) x 256
// ---------------------------------------------------------------------------
__global__ __launch_bounds__(256) void prep_kernel() {
    __shared__ __half vh_s[64][68], vl_s[64][68];
    int tid = threadIdx.x;
    int st = blockIdx.x, h = blockIdx.y, b = blockIdx.z;
    int s0 = st << 6;
    int bh = b * NHEADS + h;

    #pragma unroll
    for (int j = 0; j < 4; j++) {
        int i = tid + (j << 8);
        int row = i >> 4, d4 = (i & 15) << 2;
        const float* base = g_qkv + (size_t)(b * SEQ + s0 + row) * QKV3 + h * DHEAD + d4;
        float4 qv = *(const float4*)base;
        float4 kv = *(const float4*)(base + INNER);
        float4 vv = *(const float4*)(base + 2 * INNER);
        size_t dst = (size_t)(bh * SEQ + s0 + row) * DHEAD + d4;
        float q0h = __half2float(__float2half_rn(qv.x));
        float q1h = __half2float(__float2half_rn(qv.y));
        float q2h = __half2float(__float2half_rn(qv.z));
        float q3h = __half2float(__float2half_rn(qv.w));
        *(uint2*)(g_qh + dst) = make_uint2(packh2(qv.x, qv.y), packh2(qv.z, qv.w));
        *(uint2*)(g_ql + dst) = make_uint2(packh2(qv.x - q0h, qv.y - q1h), packh2(qv.z - q2h, qv.w - q3h));
        float k0h = __half2float(__float2half_rn(kv.x));
        float k1h = __half2float(__float2half_rn(kv.y));
        float k2h = __half2float(__float2half_rn(kv.z));
        float k3h = __half2float(__float2half_rn(kv.w));
        *(uint2*)(g_kh + dst) = make_uint2(packh2(kv.x, kv.y), packh2(kv.z, kv.w));
        *(uint2*)(g_kl + dst) = make_uint2(packh2(kv.x - k0h, kv.y - k1h), packh2(kv.z - k2h, kv.w - k3h));
        float v0h = __half2float(__float2half_rn(vv.x));
        float v1h = __half2float(__float2half_rn(vv.y));
        float v2h = __half2float(__float2half_rn(vv.z));
        float v3h = __half2float(__float2half_rn(vv.w));
        vh_s[row][d4 + 0] = __float2half_rn(vv.x);
        vh_s[row][d4 + 1] = __float2half_rn(vv.y);
        vh_s[row][d4 + 2] = __float2half_rn(vv.z);
        vh_s[row][d4 + 3] = __float2half_rn(vv.w);
        vl_s[row][d4 + 0] = __float2half_rn(vv.x - v0h);
        vl_s[row][d4 + 1] = __float2half_rn(vv.y - v1h);
        vl_s[row][d4 + 2] = __float2half_rn(vv.z - v2h);
        vl_s[row][d4 + 3] = __float2half_rn(vv.w - v3h);
    }
    __syncthreads();
    #pragma unroll
    for (int j = 0; j < 4; j++) {
        int i = tid + (j << 8);
        int drow = i >> 4, s4 = (i & 15) << 2;
        size_t dst = (size_t)(bh * DHEAD + drow) * SEQ + s0 + s4;
        __half2 h0 = __halves2half2(vh_s[s4 + 0][drow], vh_s[s4 + 1][drow]);
        __half2 h1 = __halves2half2(vh_s[s4 + 2][drow], vh_s[s4 + 3][drow]);
        *(uint2*)(g_vth + dst) = make_uint2(*(uint32_t*)&h0, *(uint32_t*)&h1);
        __half2 l0 = __halves2half2(vl_s[s4 + 0][drow], vl_s[s4 + 1][drow]);
        __half2 l1 = __halves2half2(vl_s[s4 + 2][drow], vl_s[s4 + 3][drow]);
        *(uint2*)(g_vtl + dst) = make_uint2(*(uint32_t*)&l0, *(uint32_t*)&l1);
    }
}

// ---------------------------------------------------------------------------
// 6) mma.sync fp16 flash attention (R7, proven) — epilogue emits fp16 h/l
// ---------------------------------------------------------------------------
#define SM_QH 0
#define SM_QL 16384
#define SM_KH 32768
#define SM_KL 40960
#define SM_VH 49152
#define SM_VL 57344
#define SM_TOT 65536

__device__ __forceinline__ void ld_tile64h(char* dst, const __half* src,
                                           int rstride, int tid) {
    #pragma unroll
    for (int j = 0; j < 2; j++) {
        int i = tid + (j << 8);
        int row = i >> 3, ch = i & 7;
        int off = (row << 7) + ((ch ^ (row & 7)) << 4);
        *(uint4*)(dst + off) = *(const uint4*)(src + (size_t)row * rstride + (ch << 3));
    }
}

__global__ __launch_bounds__(256) void attn_mma_kernel() {
    extern __shared__ char sm[];
    uint32_t sb = smem_u32(sm);
    int tid = threadIdx.x, warp = tid >> 5, lane = tid & 31;
    int qt = blockIdx.x, h = blockIdx.y, b = blockIdx.z;
    int q0 = qt << 7, bh = b * NHEADS + h;

    {
        const __half* qh = g_qh + (size_t)(bh * SEQ + q0) * DHEAD;
        const __half* ql = g_ql + (size_t)(bh * SEQ + q0) * DHEAD;
        #pragma unroll
        for (int j = 0; j < 4; j++) {
            int i = tid + (j << 8);
            int row = i >> 3, ch = i & 7;
            int off = (row << 7) + ((ch ^ (row & 7)) << 4);
            *(uint4*)(sm + SM_QH + off) = *(const uint4*)(qh + (size_t)row * DHEAD + (ch << 3));
            *(uint4*)(sm + SM_QL + off) = *(const uint4*)(ql + (size_t)row * DHEAD + (ch << 3));
        }
    }

    int g = lane >> 2, tg = lane & 3;
    int rw = warp << 4;
    int r0 = rw + g;
    int arow = rw + (lane & 7) + (((lane >> 3) & 1) << 3);
    int ach  = (lane >> 4);
    int asw  = arow & 7;
    uint32_t abase = (uint32_t)(arow << 7);
    int brlo = (lane & 7) + ((lane >> 4) << 3);
    int bch  = (lane >> 3) & 1;

    const float* gb2 = g_bias + h * 4096 + 2048 - q0;
    float O[8][4];
    #pragma unroll
    for (int nd = 0; nd < 8; nd++)
        #pragma unroll
        for (int e = 0; e < 4; e++) O[nd][e] = 0.f;
    float m0r = -1e30f, m1r = -1e30f, l0 = 0.f, l1 = 0.f;

    for (int kb = 0; kb < 32; kb++) {
        int k0 = kb << 6;
        __syncthreads();
        ld_tile64h(sm + SM_KH, g_kh + (size_t)(bh * SEQ + k0) * DHEAD, DHEAD, tid);
        ld_tile64h(sm + SM_KL, g_kl + (size_t)(bh * SEQ + k0) * DHEAD, DHEAD, tid);
        ld_tile64h(sm + SM_VH, g_vth + (size_t)bh * DHEAD * SEQ + k0, SEQ, tid);
        ld_tile64h(sm + SM_VL, g_vtl + (size_t)bh * DHEAD * SEQ + k0, SEQ, tid);
        __syncthreads();

        float S[8][4];
        #pragma unroll
        for (int nt = 0; nt < 8; nt++)
            #pragma unroll
            for (int e = 0; e < 4; e++) S[nt][e] = 0.f;

        #pragma unroll
        for (int ks = 0; ks < 4; ks++) {
            uint32_t qhf[4], qlf[4];
            uint32_t aoff = abase + ((((ks << 1) + ach) ^ asw) << 4);
            ldsm4(qhf, sb + SM_QH + aoff);
            ldsm4(qlf, sb + SM_QL + aoff);
            #pragma unroll
            for (int np = 0; np < 4; np++) {
                int brow = (np << 4) + brlo;
                uint32_t boff = (uint32_t)(brow << 7) + ((((ks << 1) + bch) ^ (brow & 7)) << 4);
                uint32_t kh4[4], kl4[4];
                ldsm4(kh4, sb + SM_KH + boff);
                ldsm4(kl4, sb + SM_KL + boff);
                mma_fp16(S[2 * np],     qhf, kh4);
                mma_fp16(S[2 * np],     qlf, kh4);
                mma_fp16(S[2 * np],     qhf, kl4);
                mma_fp16(S[2 * np + 1], qhf, kh4 + 2);
                mma_fp16(S[2 * np + 1], qlf, kh4 + 2);
                mma_fp16(S[2 * np + 1], qhf, kl4 + 2);
            }
        }

        float ml0 = -1e30f, ml1 = -1e30f;
        #pragma unroll
        for (int nt = 0; nt < 8; nt++) {
            int c = k0 + (nt << 3) + (tg << 1);
            S[nt][0] += __ldg(gb2 + c - r0);
            S[nt][1] += __ldg(gb2 + c + 1 - r0);
            S[nt][2] += __ldg(gb2 + c - r0 - 8);
            S[nt][3] += __ldg(gb2 + c + 1 - r0 - 8);
            ml0 = fmaxf(ml0, fmaxf(S[nt][0], S[nt][1]));
            ml1 = fmaxf(ml1, fmaxf(S[nt][2], S[nt][3]));
        }
        ml0 = fmaxf(ml0, __shfl_xor_sync(0xffffffffu, ml0, 1));
        ml0 = fmaxf(ml0, __shfl_xor_sync(0xffffffffu, ml0, 2));
        ml1 = fmaxf(ml1, __shfl_xor_sync(0xffffffffu, ml1, 1));
        ml1 = fmaxf(ml1, __shfl_xor_sync(0xffffffffu, ml1, 2));
        float mn0 = fmaxf(m0r, ml0), mn1 = fmaxf(m1r, ml1);
        float sc0 = fexp(m0r - mn0), sc1 = fexp(m1r - mn1);
        m0r = mn0; m1r = mn1;
        float rs0 = 0.f, rs1 = 0.f;
        #pragma unroll
        for (int nt = 0; nt < 8; nt++) {
            S[nt][0] = fexp(S[nt][0] - mn0);
            S[nt][1] = fexp(S[nt][1] - mn0);
            S[nt][2] = fexp(S[nt][2] - mn1);
            S[nt][3] = fexp(S[nt][3] - mn1);
            rs0 += S[nt][0] + S[nt][1];
            rs1 += S[nt][2] + S[nt][3];
        }
        l0 = l0 * sc0 + rs0;
        l1 = l1 * sc1 + rs1;
        #pragma unroll
        for (int nd = 0; nd < 8; nd++) {
            O[nd][0] *= sc0; O[nd][1] *= sc0;
            O[nd][2] *= sc1; O[nd][3] *= sc1;
        }

        uint32_t Ph[4][4], Pl[4][4];
        #pragma unroll
        for (int j = 0; j < 4; j++) {
            #pragma unroll
            for (int e = 0; e < 2; e++) {
                int nt = 2 * j + e;
                float a0 = S[nt][0], a1 = S[nt][1], a2 = S[nt][2], a3 = S[nt][3];
                float h0 = __half2float(__float2half_rn(a0));
                float h1 = __half2float(__float2half_rn(a1));
                float h2 = __half2float(__float2half_rn(a2));
                float h3 = __half2float(__float2half_rn(a3));
                Ph[j][2 * e + 0] = packh2(a0, a1);
                Ph[j][2 * e + 1] = packh2(a2, a3);
                Pl[j][2 * e + 0] = packh2(a0 - h0, a1 - h1);
                Pl[j][2 * e + 1] = packh2(a2 - h2, a3 - h3);
            }
        }

        #pragma unroll
        for (int ks = 0; ks < 4; ks++) {
            #pragma unroll
            for (int np = 0; np < 4; np++) {
                int brow = (np << 4) + brlo;
                uint32_t boff = (uint32_t)(brow << 7) + ((((ks << 1) + bch) ^ (brow & 7)) << 4);
                uint32_t vh4[4], vl4[4];
                ldsm4(vh4, sb + SM_VH + boff);
                ldsm4(vl4, sb + SM_VL + boff);
                mma_fp16(O[2 * np],     Ph[ks], vh4);
                mma_fp16(O[2 * np],     Pl[ks], vh4);
                mma_fp16(O[2 * np],     Ph[ks], vl4);
                mma_fp16(O[2 * np + 1], Ph[ks], vh4 + 2);
                mma_fp16(O[2 * np + 1], Pl[ks], vh4 + 2);
                mma_fp16(O[2 * np + 1], Ph[ks], vl4 + 2);
            }
        }
    }

    l0 += __shfl_xor_sync(0xffffffffu, l0, 1);
    l0 += __shfl_xor_sync(0xffffffffu, l0, 2);
    l1 += __shfl_xor_sync(0xffffffffu, l1, 1);
    l1 += __shfl_xor_sync(0xffffffffu, l1, 2);
    float i0 = 1.f / l0, i1 = 1.f / l1;
    size_t base0 = ((size_t)b * SEQ + q0 + r0) * INNER + h * DHEAD + (tg << 1);
    size_t base1 = base0 + 8 * INNER;
    #pragma unroll
    for (int nd = 0; nd < 8; nd++) {
        float x0 = O[nd][0] * i0, x1 = O[nd][1] * i0;
        float y0 = O[nd][2] * i1, y1 = O[nd][3] * i1;
        float xh0 = __half2float(__float2half_rn(x0));
        float xh1 = __half2float(__float2half_rn(x1));
        float yh0 = __half2float(__float2half_rn(y0));
        float yh1 = __half2float(__float2half_rn(y1));
        *(uint32_t*)(g_aih + base0 + (nd << 3)) = packh2(x0, x1);
        *(uint32_t*)(g_ail + base0 + (nd << 3)) = packh2(x0 - xh0, x1 - xh1);
        *(uint32_t*)(g_aih + base1 + (nd << 3)) = packh2(y0, y1);
        *(uint32_t*)(g_ail + base1 + (nd << 3)) = packh2(y0 - yh0, y1 - yh1);
    }
}

// ---------------------------------------------------------------------------
extern "C" void kernel_launch(void* const* d_in, const int* in_sizes, int n_in,
                              void* d_out, int out_size)
{
    const float* hidden = (const float*)d_in[0];
    const float* w_qkv  = (const float*)d_in[1];
    const float* w_o    = (const float*)d_in[2];
    const float* table  = (const float*)d_in[3];
    float* out = (float*)d_out;

    float* qkv_ptr = nullptr;
    __half *hh, *hl, *wqh, *wql, *woh, *wol, *aih, *ail;
    cudaGetSymbolAddress((void**)&qkv_ptr, g_qkv);
    cudaGetSymbolAddress((void**)&hh,  g_hh);
    cudaGetSymbolAddress((void**)&hl,  g_hl);
    cudaGetSymbolAddress((void**)&wqh, g_wqh);
    cudaGetSymbolAddress((void**)&wql, g_wql);
    cudaGetSymbolAddress((void**)&woh, g_woh);
    cudaGetSymbolAddress((void**)&wol, g_wol);
    cudaGetSymbolAddress((void**)&aih, g_aih);
    cudaGetSymbolAddress((void**)&ail, g_ail);

    cudaFuncSetAttribute(attn_mma_kernel,
                         cudaFuncAttributeMaxDynamicSharedMemorySize, SM_TOT);
    cudaFuncSetAttribute(gemm_fp16x3_kernel,
                         cudaFuncAttributeMaxDynamicSharedMemorySize, GS_TOT);

    bias_fill_kernel<<<16, 256>>>(table);
    bias_write_kernel<<<dim3(SEQ, NHEADS), 512>>>(out + (size_t)BATCH * SEQ * DMODEL);
    hsplit_kernel<<<(BATCH * SEQ * DMODEL) / 1024, 256>>>(hidden);
    wsplit_kernel<<<dim3(QKV3 / 64, DMODEL / 64), 256>>>(w_qkv, wqh, wql, QKV3);
    wsplit_kernel<<<dim3(INNER / 64, DMODEL / 64), 256>>>(w_o, woh, wol, INNER);
    // QKV projection (fp16x3 tensor cores)
    gemm_fp16x3_kernel<<<dim3(QKV3 / 64, (BATCH * SEQ) / 128), 256, GS_TOT>>>(
        hh, hl, wqh, wql, qkv_ptr, QKV3, DMODEL);
    prep_kernel<<<dim3(32, NHEADS, BATCH), 256>>>();
    attn_mma_kernel<<<dim3(16, NHEADS, BATCH), 256, SM_TOT>>>();
    // output projection
    gemm_fp16x3_kernel<<<dim3(DMODEL / 64, (BATCH * SEQ) / 128), 256, GS_TOT>>>(
        aih, ail, woh, wol, out, DMODEL, INNER);
}

// round 13
// speedup vs baseline: 4.5628x; 1.1680x over previous
#include <cuda_runtime.h>
#include <cuda_fp16.h>
#include <math.h>
#include <stdint.h>

#define BATCH   2
#define SEQ     2048
#define DMODEL  1024
#define NHEADS  16
#define DHEAD   64
#define INNER   1024
#define QKV3    3072
#define BH      (BATCH * NHEADS)

// -------- scratch (device globals; no allocation allowed) --------
__device__ float g_qkv[(size_t)BATCH * SEQ * QKV3];   // 48 MB
__device__ float g_bias[NHEADS * 4096];               // 256 KB
__device__ __half g_qh[(size_t)BH * SEQ * DHEAD];
__device__ __half g_ql[(size_t)BH * SEQ * DHEAD];
__device__ __half g_kh[(size_t)BH * SEQ * DHEAD];
__device__ __half g_kl[(size_t)BH * SEQ * DHEAD];
__device__ __half g_vth[(size_t)BH * DHEAD * SEQ];    // V^T [bh][d][s]
__device__ __half g_vtl[(size_t)BH * DHEAD * SEQ];
__device__ __half g_hh[(size_t)BATCH * SEQ * DMODEL];
__device__ __half g_hl[(size_t)BATCH * SEQ * DMODEL];
__device__ __half g_wqh[(size_t)QKV3 * DMODEL];
__device__ __half g_wql[(size_t)QKV3 * DMODEL];
__device__ __half g_woh[(size_t)DMODEL * INNER];
__device__ __half g_wol[(size_t)DMODEL * INNER];
__device__ __half g_aih[(size_t)BATCH * SEQ * INNER];
__device__ __half g_ail[(size_t)BATCH * SEQ * INNER];

__device__ __forceinline__ uint32_t smem_u32(const void* p) {
    uint32_t a;
    asm("{ .reg .u64 t; cvta.to.shared.u64 t, %1; cvt.u32.u64 %0, t; }" : "=r"(a) : "l"(p));
    return a;
}
__device__ __forceinline__ uint32_t packh2(float lo, float hi) {
    __half2 p = __halves2half2(__float2half_rn(lo), __float2half_rn(hi));
    return *(uint32_t*)&p;
}
__device__ __forceinline__ void ldsm4(uint32_t* r, uint32_t a) {
    asm volatile("ldmatrix.sync.aligned.m8n8.x4.shared.b16 {%0,%1,%2,%3}, [%4];"
        : "=r"(r[0]), "=r"(r[1]), "=r"(r[2]), "=r"(r[3]) : "r"(a));
}
__device__ __forceinline__ void mma_fp16(float* d, const uint32_t* a, const uint32_t* b) {
    asm volatile("mma.sync.aligned.m16n8k16.row.col.f32.f16.f16.f32 "
        "{%0,%1,%2,%3},{%4,%5,%6,%7},{%8,%9},{%0,%1,%2,%3};"
        : "+f"(d[0]), "+f"(d[1]), "+f"(d[2]), "+f"(d[3])
        : "r"(a[0]), "r"(a[1]), "r"(a[2]), "r"(a[3]), "r"(b[0]), "r"(b[1]));
}
#define CP16(dst, src) \
    asm volatile("cp.async.cg.shared.global [%0], [%1], 16;" :: "r"(dst), "l"(src))
#define CP_COMMIT() asm volatile("cp.async.commit_group;" ::: "memory")
#define CP_WAIT0()  asm volatile("cp.async.wait_group 0;" ::: "memory")

// FMA-pipe exp (no MUFU)
__device__ __forceinline__ float fexp(float x) {
    x = fmaxf(x, -87.0f);
    float t  = x * 1.4426950408889634f;
    float fn = t + 12582912.0f;
    int   ni = __float_as_int(fn) - 0x4B400000;
    float f  = t - (fn - 12582912.0f);
    float p  = 9.6784e-3f;
    p = fmaf(p, f, 5.550411e-2f);
    p = fmaf(p, f, 2.4022651e-1f);
    p = fmaf(p, f, 6.9314718e-1f);
    p = fmaf(p, f, 1.0f);
    return __int_as_float(__float_as_int(p) + (ni << 23));
}

// ---------------------------------------------------------------------------
// 1) bias table
// ---------------------------------------------------------------------------
__global__ void bias_fill_kernel(const float* __restrict__ table) {
    int idx = blockIdx.x * blockDim.x + threadIdx.x;
    if (idx >= 4096) return;
    int rel = idx - 2048;
    int bucket = (rel > 0) ? 16 : 0;
    int ad = rel < 0 ? -rel : rel;
    int bb;
    if (ad < 8) {
        bb = ad;
    } else {
        float rp = (float)ad;
        float l  = (float)log((double)(rp / 8.0f));
        float v  = (l / 2.7725887f) * 8.0f;
        bb = 8 + (int)v;
        if (bb > 15) bb = 15;
    }
    bucket += bb;
    #pragma unroll
    for (int h = 0; h < NHEADS; h++)
        g_bias[h * 4096 + idx] = table[bucket * NHEADS + h];
}

// ---------------------------------------------------------------------------
// 2) position_bias output
// ---------------------------------------------------------------------------
__global__ void bias_write_kernel(float* __restrict__ out) {
    int q = blockIdx.x;
    int h = blockIdx.y;
    int k = threadIdx.x << 2;
    const float* src = g_bias + h * 4096 + (2048 - q) + k;
    float4 v = make_float4(src[0], src[1], src[2], src[3]);
    *(float4*)(out + ((size_t)h * SEQ + q) * SEQ + k) = v;
}

// ---------------------------------------------------------------------------
// 3a) hidden split
// ---------------------------------------------------------------------------
__global__ __launch_bounds__(256) void hsplit_kernel(const float* __restrict__ src) {
    size_t i = ((size_t)blockIdx.x * 256 + threadIdx.x) << 2;
    float4 v = *(const float4*)(src + i);
    float h0 = __half2float(__float2half_rn(v.x));
    float h1 = __half2float(__float2half_rn(v.y));
    float h2 = __half2float(__float2half_rn(v.z));
    float h3 = __half2float(__float2half_rn(v.w));
    *(uint2*)(g_hh + i) = make_uint2(packh2(v.x, v.y), packh2(v.z, v.w));
    *(uint2*)(g_hl + i) = make_uint2(packh2(v.x - h0, v.y - h1), packh2(v.z - h2, v.w - h3));
}

// ---------------------------------------------------------------------------
// 3b) weight transpose + split
// ---------------------------------------------------------------------------
__global__ __launch_bounds__(256) void wsplit_kernel(
    const float* __restrict__ w, __half* __restrict__ outh,
    __half* __restrict__ outl, int N)
{
    __shared__ float st[64][68];
    int tid = threadIdx.x;
    int n0 = blockIdx.x << 6, k0 = blockIdx.y << 6;
    #pragma unroll
    for (int j = 0; j < 4; j++) {
        int i = tid + (j << 8);
        int kr = i >> 4, nc = (i & 15) << 2;
        float4 v = *(const float4*)(w + (size_t)(k0 + kr) * N + n0 + nc);
        st[nc + 0][kr] = v.x;
        st[nc + 1][kr] = v.y;
        st[nc + 2][kr] = v.z;
        st[nc + 3][kr] = v.w;
    }
    __syncthreads();
    #pragma unroll
    for (int j = 0; j < 4; j++) {
        int i = tid + (j << 8);
        int nr = i >> 4, kc = (i & 15) << 2;
        float a = st[nr][kc], b = st[nr][kc + 1], c = st[nr][kc + 2], d = st[nr][kc + 3];
        float ha = __half2float(__float2half_rn(a));
        float hb = __half2float(__float2half_rn(b));
        float hc = __half2float(__float2half_rn(c));
        float hd = __half2float(__float2half_rn(d));
        size_t dst = (size_t)(n0 + nr) * DMODEL + k0 + kc;
        *(uint2*)(outh + dst) = make_uint2(packh2(a, b), packh2(c, d));
        *(uint2*)(outl + dst) = make_uint2(packh2(a - ha, b - hb), packh2(c - hc, d - hd));
    }
}

// ---------------------------------------------------------------------------
// 4) fp16x3 GEMM with cp.async double buffering
//    CTA 128m x 64n, K-chunk 64; buffers: [Ah 16K | Al 16K | Bh 8K | Bl 8K] x2
// ---------------------------------------------------------------------------
#define GB_AH 0
#define GB_AL 16384
#define GB_BH 32768
#define GB_BL 40960
#define GB_STRIDE 49152
#define GS_TOT 98304

__global__ __launch_bounds__(256) void gemm_fp16x3_kernel(
    const __half* __restrict__ Ah, const __half* __restrict__ Al,
    const __half* __restrict__ Bh, const __half* __restrict__ Bl,
    float* __restrict__ C, int N, int K)
{
    extern __shared__ char sm[];
    uint32_t sb = smem_u32(sm);
    int tid = threadIdx.x, warp = tid >> 5, lane = tid & 31;
    int bn = blockIdx.x << 6, bm = blockIdx.y << 7;
    int wm = warp >> 1, wn = warp & 1;

    int arow_l = (lane & 15), ach = lane >> 4;
    int brlo = (lane & 7) + ((lane >> 4) << 3), bch = (lane >> 3) & 1;
    int g = lane >> 2, tg = lane & 3;

    float acc[2][4][4];
    #pragma unroll
    for (int mi = 0; mi < 2; mi++)
        #pragma unroll
        for (int nb = 0; nb < 4; nb++)
            #pragma unroll
            for (int e = 0; e < 4; e++) acc[mi][nb][e] = 0.f;

    // prologue: prefetch chunk 0 into buffer 0
    {
        uint32_t dst = sb;
        #pragma unroll
        for (int j = 0; j < 4; j++) {
            int i = tid + (j << 8);
            int row = i >> 3, ch = i & 7;
            int off = (row << 7) + ((ch ^ (row & 7)) << 4);
            CP16(dst + GB_AH + off, Ah + (size_t)(bm + row) * K + (ch << 3));
            CP16(dst + GB_AL + off, Al + (size_t)(bm + row) * K + (ch << 3));
        }
        #pragma unroll
        for (int j = 0; j < 2; j++) {
            int i = tid + (j << 8);
            int row = i >> 3, ch = i & 7;
            int off = (row << 7) + ((ch ^ (row & 7)) << 4);
            CP16(dst + GB_BH + off, Bh + (size_t)(bn + row) * K + (ch << 3));
            CP16(dst + GB_BL + off, Bl + (size_t)(bn + row) * K + (ch << 3));
        }
        CP_COMMIT();
    }

    int buf = 0;
    int nchunks = K >> 6;
    for (int c = 0; c < nchunks; c++) {
        CP_WAIT0();
        __syncthreads();
        if (c + 1 < nchunks) {
            int k1 = (c + 1) << 6;
            uint32_t dst = sb + (buf ^ 1) * GB_STRIDE;
            #pragma unroll
            for (int j = 0; j < 4; j++) {
                int i = tid + (j << 8);
                int row = i >> 3, ch = i & 7;
                int off = (row << 7) + ((ch ^ (row & 7)) << 4);
                CP16(dst + GB_AH + off, Ah + (size_t)(bm + row) * K + k1 + (ch << 3));
                CP16(dst + GB_AL + off, Al + (size_t)(bm + row) * K + k1 + (ch << 3));
            }
            #pragma unroll
            for (int j = 0; j < 2; j++) {
                int i = tid + (j << 8);
                int row = i >> 3, ch = i & 7;
                int off = (row << 7) + ((ch ^ (row & 7)) << 4);
                CP16(dst + GB_BH + off, Bh + (size_t)(bn + row) * K + k1 + (ch << 3));
                CP16(dst + GB_BL + off, Bl + (size_t)(bn + row) * K + k1 + (ch << 3));
            }
            CP_COMMIT();
        }
        uint32_t base = sb + buf * GB_STRIDE;

        #pragma unroll
        for (int ks = 0; ks < 4; ks++) {
            uint32_t ah[2][4], al[2][4], bh4[2][4], bl4[2][4];
            #pragma unroll
            for (int mi = 0; mi < 2; mi++) {
                int arow = (wm << 5) + (mi << 4) + arow_l;
                uint32_t aoff = (uint32_t)(arow << 7) + ((((ks << 1) + ach) ^ (arow & 7)) << 4);
                ldsm4(ah[mi], base + GB_AH + aoff);
                ldsm4(al[mi], base + GB_AL + aoff);
            }
            #pragma unroll
            for (int np = 0; np < 2; np++) {
                int brow = (wn << 5) + (np << 4) + brlo;
                uint32_t boff = (uint32_t)(brow << 7) + ((((ks << 1) + bch) ^ (brow & 7)) << 4);
                ldsm4(bh4[np], base + GB_BH + boff);
                ldsm4(bl4[np], base + GB_BL + boff);
            }
            #pragma unroll
            for (int mi = 0; mi < 2; mi++)
                #pragma unroll
                for (int np = 0; np < 2; np++) {
                    mma_fp16(acc[mi][2 * np],     ah[mi], bh4[np]);
                    mma_fp16(acc[mi][2 * np],     al[mi], bh4[np]);
                    mma_fp16(acc[mi][2 * np],     ah[mi], bl4[np]);
                    mma_fp16(acc[mi][2 * np + 1], ah[mi], bh4[np] + 2);
                    mma_fp16(acc[mi][2 * np + 1], al[mi], bh4[np] + 2);
                    mma_fp16(acc[mi][2 * np + 1], ah[mi], bl4[np] + 2);
                }
        }
        buf ^= 1;
    }

    #pragma unroll
    for (int mi = 0; mi < 2; mi++) {
        int r = bm + (wm << 5) + (mi << 4) + g;
        #pragma unroll
        for (int nb = 0; nb < 4; nb++) {
            int c = bn + (wn << 5) + (nb << 3) + (tg << 1);
            *(float2*)&C[(size_t)r * N + c]       = make_float2(acc[mi][nb][0], acc[mi][nb][1]);
            *(float2*)&C[(size_t)(r + 8) * N + c] = make_float2(acc[mi][nb][2], acc[mi][nb][3]);
        }
    }
}

// ---------------------------------------------------------------------------
// 5) Prep: split Q,K fp16 hi/lo; V transposed hi/lo
// ---------------------------------------------------------------------------
__global__ __launch_bounds__(256) void prep_kernel() {
    __shared__ __half vh_s[64][68], vl_s[64][68];
    int tid = threadIdx.x;
    int st = blockIdx.x, h = blockIdx.y, b = blockIdx.z;
    int s0 = st << 6;
    int bh = b * NHEADS + h;

    #pragma unroll
    for (int j = 0; j < 4; j++) {
        int i = tid + (j << 8);
        int row = i >> 4, d4 = (i & 15) << 2;
        const float* base = g_qkv + (size_t)(b * SEQ + s0 + row) * QKV3 + h * DHEAD + d4;
        float4 qv = *(const float4*)base;
        float4 kv = *(const float4*)(base + INNER);
        float4 vv = *(const float4*)(base + 2 * INNER);
        size_t dst = (size_t)(bh * SEQ + s0 + row) * DHEAD + d4;
        float q0h = __half2float(__float2half_rn(qv.x));
        float q1h = __half2float(__float2half_rn(qv.y));
        float q2h = __half2float(__float2half_rn(qv.z));
        float q3h = __half2float(__float2half_rn(qv.w));
        *(uint2*)(g_qh + dst) = make_uint2(packh2(qv.x, qv.y), packh2(qv.z, qv.w));
        *(uint2*)(g_ql + dst) = make_uint2(packh2(qv.x - q0h, qv.y - q1h), packh2(qv.z - q2h, qv.w - q3h));
        float k0h = __half2float(__float2half_rn(kv.x));
        float k1h = __half2float(__float2half_rn(kv.y));
        float k2h = __half2float(__float2half_rn(kv.z));
        float k3h = __half2float(__float2half_rn(kv.w));
        *(uint2*)(g_kh + dst) = make_uint2(packh2(kv.x, kv.y), packh2(kv.z, kv.w));
        *(uint2*)(g_kl + dst) = make_uint2(packh2(kv.x - k0h, kv.y - k1h), packh2(kv.z - k2h, kv.w - k3h));
        float v0h = __half2float(__float2half_rn(vv.x));
        float v1h = __half2float(__float2half_rn(vv.y));
        float v2h = __half2float(__float2half_rn(vv.z));
        float v3h = __half2float(__float2half_rn(vv.w));
        vh_s[row][d4 + 0] = __float2half_rn(vv.x);
        vh_s[row][d4 + 1] = __float2half_rn(vv.y);
        vh_s[row][d4 + 2] = __float2half_rn(vv.z);
        vh_s[row][d4 + 3] = __float2half_rn(vv.w);
        vl_s[row][d4 + 0] = __float2half_rn(vv.x - v0h);
        vl_s[row][d4 + 1] = __float2half_rn(vv.y - v1h);
        vl_s[row][d4 + 2] = __float2half_rn(vv.z - v2h);
        vl_s[row][d4 + 3] = __float2half_rn(vv.w - v3h);
    }
    __syncthreads();
    #pragma unroll
    for (int j = 0; j < 4; j++) {
        int i = tid + (j << 8);
        int drow = i >> 4, s4 = (i & 15) << 2;
        size_t dst = (size_t)(bh * DHEAD + drow) * SEQ + s0 + s4;
        __half2 h0 = __halves2half2(vh_s[s4 + 0][drow], vh_s[s4 + 1][drow]);
        __half2 h1 = __halves2half2(vh_s[s4 + 2][drow], vh_s[s4 + 3][drow]);
        *(uint2*)(g_vth + dst) = make_uint2(*(uint32_t*)&h0, *(uint32_t*)&h1);
        __half2 l0 = __halves2half2(vl_s[s4 + 0][drow], vl_s[s4 + 1][drow]);
        __half2 l1 = __halves2half2(vl_s[s4 + 2][drow], vl_s[s4 + 3][drow]);
        *(uint2*)(g_vtl + dst) = make_uint2(*(uint32_t*)&l0, *(uint32_t*)&l1);
    }
}

// ---------------------------------------------------------------------------
// 6) fp16 flash attention with cp.async double-buffered K/V
//    smem: Q 32K | KV buf0 32K | KV buf1 32K = 96KB
// ---------------------------------------------------------------------------
#define SM_QH 0
#define SM_QL 16384
#define SM_KV 32768
#define KV_KH 0
#define KV_KL 8192
#define KV_VH 16384
#define KV_VL 24576
#define KV_STRIDE 32768
#define SM_TOT 98304

__device__ __forceinline__ void prefetch_kv(uint32_t dst, int bh, int k0, int tid) {
    const __half* kh  = g_kh  + ((size_t)bh * SEQ + k0) * DHEAD;
    const __half* kl  = g_kl  + ((size_t)bh * SEQ + k0) * DHEAD;
    const __half* vth = g_vth + (size_t)bh * DHEAD * SEQ + k0;
    const __half* vtl = g_vtl + (size_t)bh * DHEAD * SEQ + k0;
    #pragma unroll
    for (int j = 0; j < 2; j++) {
        int i = tid + (j << 8);
        int row = i >> 3, ch = i & 7;
        int off = (row << 7) + ((ch ^ (row & 7)) << 4);
        CP16(dst + KV_KH + off, kh  + (size_t)row * DHEAD + (ch << 3));
        CP16(dst + KV_KL + off, kl  + (size_t)row * DHEAD + (ch << 3));
        CP16(dst + KV_VH + off, vth + (size_t)row * SEQ   + (ch << 3));
        CP16(dst + KV_VL + off, vtl + (size_t)row * SEQ   + (ch << 3));
    }
}

__global__ __launch_bounds__(256) void attn_mma_kernel() {
    extern __shared__ char sm[];
    uint32_t sb = smem_u32(sm);
    int tid = threadIdx.x, warp = tid >> 5, lane = tid & 31;
    int qt = blockIdx.x, h = blockIdx.y, b = blockIdx.z;
    int q0 = qt << 7, bh = b * NHEADS + h;

    // prologue: Q tile (regular stores) + prefetch kb=0
    {
        const __half* qh = g_qh + (size_t)(bh * SEQ + q0) * DHEAD;
        const __half* ql = g_ql + (size_t)(bh * SEQ + q0) * DHEAD;
        #pragma unroll
        for (int j = 0; j < 4; j++) {
            int i = tid + (j << 8);
            int row = i >> 3, ch = i & 7;
            int off = (row << 7) + ((ch ^ (row & 7)) << 4);
            *(uint4*)(sm + SM_QH + off) = *(const uint4*)(qh + (size_t)row * DHEAD + (ch << 3));
            *(uint4*)(sm + SM_QL + off) = *(const uint4*)(ql + (size_t)row * DHEAD + (ch << 3));
        }
    }
    prefetch_kv(sb + SM_KV, bh, 0, tid);
    CP_COMMIT();

    int g = lane >> 2, tg = lane & 3;
    int rw = warp << 4;
    int r0 = rw + g;
    int arow = rw + (lane & 7) + (((lane >> 3) & 1) << 3);
    int ach  = (lane >> 4);
    int asw  = arow & 7;
    uint32_t abase = (uint32_t)(arow << 7);
    int brlo = (lane & 7) + ((lane >> 4) << 3);
    int bch  = (lane >> 3) & 1;

    const float* gb2 = g_bias + h * 4096 + 2048 - q0;
    float O[8][4];
    #pragma unroll
    for (int nd = 0; nd < 8; nd++)
        #pragma unroll
        for (int e = 0; e < 4; e++) O[nd][e] = 0.f;
    float m0r = -1e30f, m1r = -1e30f, l0 = 0.f, l1 = 0.f;

    int buf = 0;
    for (int kb = 0; kb < 32; kb++) {
        int k0 = kb << 6;
        CP_WAIT0();
        __syncthreads();
        if (kb < 31) {
            prefetch_kv(sb + SM_KV + (buf ^ 1) * KV_STRIDE, bh, k0 + 64, tid);
            CP_COMMIT();
        }
        uint32_t kvb = sb + SM_KV + buf * KV_STRIDE;

        float S[8][4];
        #pragma unroll
        for (int nt = 0; nt < 8; nt++)
            #pragma unroll
            for (int e = 0; e < 4; e++) S[nt][e] = 0.f;

        #pragma unroll
        for (int ks = 0; ks < 4; ks++) {
            uint32_t qhf[4], qlf[4];
            uint32_t aoff = abase + ((((ks << 1) + ach) ^ asw) << 4);
            ldsm4(qhf, sb + SM_QH + aoff);
            ldsm4(qlf, sb + SM_QL + aoff);
            #pragma unroll
            for (int np = 0; np < 4; np++) {
                int brow = (np << 4) + brlo;
                uint32_t boff = (uint32_t)(brow << 7) + ((((ks << 1) + bch) ^ (brow & 7)) << 4);
                uint32_t kh4[4], kl4[4];
                ldsm4(kh4, kvb + KV_KH + boff);
                ldsm4(kl4, kvb + KV_KL + boff);
                mma_fp16(S[2 * np],     qhf, kh4);
                mma_fp16(S[2 * np],     qlf, kh4);
                mma_fp16(S[2 * np],     qhf, kl4);
                mma_fp16(S[2 * np + 1], qhf, kh4 + 2);
                mma_fp16(S[2 * np + 1], qlf, kh4 + 2);
                mma_fp16(S[2 * np + 1], qhf, kl4 + 2);
            }
        }

        float ml0 = -1e30f, ml1 = -1e30f;
        #pragma unroll
        for (int nt = 0; nt < 8; nt++) {
            int c = k0 + (nt << 3) + (tg << 1);
            S[nt][0] += __ldg(gb2 + c - r0);
            S[nt][1] += __ldg(gb2 + c + 1 - r0);
            S[nt][2] += __ldg(gb2 + c - r0 - 8);
            S[nt][3] += __ldg(gb2 + c + 1 - r0 - 8);
            ml0 = fmaxf(ml0, fmaxf(S[nt][0], S[nt][1]));
            ml1 = fmaxf(ml1, fmaxf(S[nt][2], S[nt][3]));
        }
        ml0 = fmaxf(ml0, __shfl_xor_sync(0xffffffffu, ml0, 1));
        ml0 = fmaxf(ml0, __shfl_xor_sync(0xffffffffu, ml0, 2));
        ml1 = fmaxf(ml1, __shfl_xor_sync(0xffffffffu, ml1, 1));
        ml1 = fmaxf(ml1, __shfl_xor_sync(0xffffffffu, ml1, 2));
        float mn0 = fmaxf(m0r, ml0), mn1 = fmaxf(m1r, ml1);
        float sc0 = fexp(m0r - mn0), sc1 = fexp(m1r - mn1);
        m0r = mn0; m1r = mn1;
        float rs0 = 0.f, rs1 = 0.f;
        #pragma unroll
        for (int nt = 0; nt < 8; nt++) {
            S[nt][0] = fexp(S[nt][0] - mn0);
            S[nt][1] = fexp(S[nt][1] - mn0);
            S[nt][2] = fexp(S[nt][2] - mn1);
            S[nt][3] = fexp(S[nt][3] - mn1);
            rs0 += S[nt][0] + S[nt][1];
            rs1 += S[nt][2] + S[nt][3];
        }
        l0 = l0 * sc0 + rs0;
        l1 = l1 * sc1 + rs1;
        #pragma unroll
        for (int nd = 0; nd < 8; nd++) {
            O[nd][0] *= sc0; O[nd][1] *= sc0;
            O[nd][2] *= sc1; O[nd][3] *= sc1;
        }

        uint32_t Ph[4][4], Pl[4][4];
        #pragma unroll
        for (int j = 0; j < 4; j++) {
            #pragma unroll
            for (int e = 0; e < 2; e++) {
                int nt = 2 * j + e;
                float a0 = S[nt][0], a1 = S[nt][1], a2 = S[nt][2], a3 = S[nt][3];
                float h0 = __half2float(__float2half_rn(a0));
                float h1 = __half2float(__float2half_rn(a1));
                float h2 = __half2float(__float2half_rn(a2));
                float h3 = __half2float(__float2half_rn(a3));
                Ph[j][2 * e + 0] = packh2(a0, a1);
                Ph[j][2 * e + 1] = packh2(a2, a3);
                Pl[j][2 * e + 0] = packh2(a0 - h0, a1 - h1);
                Pl[j][2 * e + 1] = packh2(a2 - h2, a3 - h3);
            }
        }

        #pragma unroll
        for (int ks = 0; ks < 4; ks++) {
            #pragma unroll
            for (int np = 0; np < 4; np++) {
                int brow = (np << 4) + brlo;
                uint32_t boff = (uint32_t)(brow << 7) + ((((ks << 1) + bch) ^ (brow & 7)) << 4);
                uint32_t vh4[4], vl4[4];
                ldsm4(vh4, kvb + KV_VH + boff);
                ldsm4(vl4, kvb + KV_VL + boff);
                mma_fp16(O[2 * np],     Ph[ks], vh4);
                mma_fp16(O[2 * np],     Pl[ks], vh4);
                mma_fp16(O[2 * np],     Ph[ks], vl4);
                mma_fp16(O[2 * np + 1], Ph[ks], vh4 + 2);
                mma_fp16(O[2 * np + 1], Pl[ks], vh4 + 2);
                mma_fp16(O[2 * np + 1], Ph[ks], vl4 + 2);
            }
        }
        buf ^= 1;
    }

    l0 += __shfl_xor_sync(0xffffffffu, l0, 1);
    l0 += __shfl_xor_sync(0xffffffffu, l0, 2);
    l1 += __shfl_xor_sync(0xffffffffu, l1, 1);
    l1 += __shfl_xor_sync(0xffffffffu, l1, 2);
    float i0 = 1.f / l0, i1 = 1.f / l1;
    size_t base0 = ((size_t)b * SEQ + q0 + r0) * INNER + h * DHEAD + (tg << 1);
    size_t base1 = base0 + 8 * INNER;
    #pragma unroll
    for (int nd = 0; nd < 8; nd++) {
        float x0 = O[nd][0] * i0, x1 = O[nd][1] * i0;
        float y0 = O[nd][2] * i1, y1 = O[nd][3] * i1;
        float xh0 = __half2float(__float2half_rn(x0));
        float xh1 = __half2float(__float2half_rn(x1));
        float yh0 = __half2float(__float2half_rn(y0));
        float yh1 = __half2float(__float2half_rn(y1));
        *(uint32_t*)(g_aih + base0 + (nd << 3)) = packh2(x0, x1);
        *(uint32_t*)(g_ail + base0 + (nd << 3)) = packh2(x0 - xh0, x1 - xh1);
        *(uint32_t*)(g_aih + base1 + (nd << 3)) = packh2(y0, y1);
        *(uint32_t*)(g_ail + base1 + (nd << 3)) = packh2(y0 - yh0, y1 - yh1);
    }
}

// ---------------------------------------------------------------------------
extern "C" void kernel_launch(void* const* d_in, const int* in_sizes, int n_in,
                              void* d_out, int out_size)
{
    const float* hidden = (const float*)d_in[0];
    const float* w_qkv  = (const float*)d_in[1];
    const float* w_o    = (const float*)d_in[2];
    const float* table  = (const float*)d_in[3];
    float* out = (float*)d_out;

    float* qkv_ptr = nullptr;
    __half *hh, *hl, *wqh, *wql, *woh, *wol, *aih, *ail;
    cudaGetSymbolAddress((void**)&qkv_ptr, g_qkv);
    cudaGetSymbolAddress((void**)&hh,  g_hh);
    cudaGetSymbolAddress((void**)&hl,  g_hl);
    cudaGetSymbolAddress((void**)&wqh, g_wqh);
    cudaGetSymbolAddress((void**)&wql, g_wql);
    cudaGetSymbolAddress((void**)&woh, g_woh);
    cudaGetSymbolAddress((void**)&wol, g_wol);
    cudaGetSymbolAddress((void**)&aih, g_aih);
    cudaGetSymbolAddress((void**)&ail, g_ail);

    cudaFuncSetAttribute(attn_mma_kernel,
                         cudaFuncAttributeMaxDynamicSharedMemorySize, SM_TOT);
    cudaFuncSetAttribute(gemm_fp16x3_kernel,
                         cudaFuncAttributeMaxDynamicSharedMemorySize, GS_TOT);

    bias_fill_kernel<<<16, 256>>>(table);
    bias_write_kernel<<<dim3(SEQ, NHEADS), 512>>>(out + (size_t)BATCH * SEQ * DMODEL);
    hsplit_kernel<<<(BATCH * SEQ * DMODEL) / 1024, 256>>>(hidden);
    wsplit_kernel<<<dim3(QKV3 / 64, DMODEL / 64), 256>>>(w_qkv, wqh, wql, QKV3);
    wsplit_kernel<<<dim3(INNER / 64, DMODEL / 64), 256>>>(w_o, woh, wol, INNER);
    gemm_fp16x3_kernel<<<dim3(QKV3 / 64, (BATCH * SEQ) / 128), 256, GS_TOT>>>(
        hh, hl, wqh, wql, qkv_ptr, QKV3, DMODEL);
    prep_kernel<<<dim3(32, NHEADS, BATCH), 256>>>();
    attn_mma_kernel<<<dim3(16, NHEADS, BATCH), 256, SM_TOT>>>();
    gemm_fp16x3_kernel<<<dim3(DMODEL / 64, (BATCH * SEQ) / 128), 256, GS_TOT>>>(
        aih, ail, woh, wol, out, DMODEL, INNER);
}

// round 16
// speedup vs baseline: 4.6991x; 1.0299x over previous
#include <cuda_runtime.h>
#include <cuda_fp16.h>
#include <math.h>
#include <stdint.h>

#define BATCH   2
#define SEQ     2048
#define DMODEL  1024
#define NHEADS  16
#define DHEAD   64
#define INNER   1024
#define QKV3    3072
#define BH      (BATCH * NHEADS)

// -------- scratch (device globals; no allocation allowed) --------
__device__ float g_qkv[(size_t)BATCH * SEQ * QKV3];   // 48 MB
__device__ float g_bias[NHEADS * 4096];               // 256 KB
__device__ __half g_qh[(size_t)BH * SEQ * DHEAD];
__device__ __half g_ql[(size_t)BH * SEQ * DHEAD];
__device__ __half g_kh[(size_t)BH * SEQ * DHEAD];
__device__ __half g_kl[(size_t)BH * SEQ * DHEAD];
__device__ __half g_vth[(size_t)BH * DHEAD * SEQ];    // V^T [bh][d][s]
__device__ __half g_vtl[(size_t)BH * DHEAD * SEQ];
__device__ __half g_hh[(size_t)BATCH * SEQ * DMODEL];
__device__ __half g_hl[(size_t)BATCH * SEQ * DMODEL];
__device__ __half g_wqh[(size_t)QKV3 * DMODEL];
__device__ __half g_wql[(size_t)QKV3 * DMODEL];
__device__ __half g_woh[(size_t)DMODEL * INNER];
__device__ __half g_wol[(size_t)DMODEL * INNER];
__device__ __half g_aih[(size_t)BATCH * SEQ * INNER];
__device__ __half g_ail[(size_t)BATCH * SEQ * INNER];

__device__ __forceinline__ uint32_t smem_u32(const void* p) {
    uint32_t a;
    asm("{ .reg .u64 t; cvta.to.shared.u64 t, %1; cvt.u32.u64 %0, t; }" : "=r"(a) : "l"(p));
    return a;
}
__device__ __forceinline__ uint32_t packh2(float lo, float hi) {
    __half2 p = __halves2half2(__float2half_rn(lo), __float2half_rn(hi));
    return *(uint32_t*)&p;
}
__device__ __forceinline__ void ldsm4(uint32_t* r, uint32_t a) {
    asm volatile("ldmatrix.sync.aligned.m8n8.x4.shared.b16 {%0,%1,%2,%3}, [%4];"
        : "=r"(r[0]), "=r"(r[1]), "=r"(r[2]), "=r"(r[3]) : "r"(a));
}
__device__ __forceinline__ void mma_fp16(float* d, const uint32_t* a, const uint32_t* b) {
    asm volatile("mma.sync.aligned.m16n8k16.row.col.f32.f16.f16.f32 "
        "{%0,%1,%2,%3},{%4,%5,%6,%7},{%8,%9},{%0,%1,%2,%3};"
        : "+f"(d[0]), "+f"(d[1]), "+f"(d[2]), "+f"(d[3])
        : "r"(a[0]), "r"(a[1]), "r"(a[2]), "r"(a[3]), "r"(b[0]), "r"(b[1]));
}
__device__ __forceinline__ void mma_fp16_e(float* d,
    uint32_t a0, uint32_t a1, uint32_t a2, uint32_t a3,
    uint32_t b0, uint32_t b1) {
    asm volatile("mma.sync.aligned.m16n8k16.row.col.f32.f16.f16.f32 "
        "{%0,%1,%2,%3},{%4,%5,%6,%7},{%8,%9},{%0,%1,%2,%3};"
        : "+f"(d[0]), "+f"(d[1]), "+f"(d[2]), "+f"(d[3])
        : "r"(a0), "r"(a1), "r"(a2), "r"(a3), "r"(b0), "r"(b1));
}
#define CP16(dst, src) \
    asm volatile("cp.async.cg.shared.global [%0], [%1], 16;" :: "r"(dst), "l"(src))
#define CP_COMMIT() asm volatile("cp.async.commit_group;" ::: "memory")
#define CP_WAIT0()  asm volatile("cp.async.wait_group 0;" ::: "memory")

// FMA-pipe exp (no MUFU)
__device__ __forceinline__ float fexp(float x) {
    x = fmaxf(x, -87.0f);
    float t  = x * 1.4426950408889634f;
    float fn = t + 12582912.0f;
    int   ni = __float_as_int(fn) - 0x4B400000;
    float f  = t - (fn - 12582912.0f);
    float p  = 9.6784e-3f;
    p = fmaf(p, f, 5.550411e-2f);
    p = fmaf(p, f, 2.4022651e-1f);
    p = fmaf(p, f, 6.9314718e-1f);
    p = fmaf(p, f, 1.0f);
    return __int_as_float(__float_as_int(p) + (ni << 23));
}

// ---------------------------------------------------------------------------
// 1) bias table
// ---------------------------------------------------------------------------
__global__ void bias_fill_kernel(const float* __restrict__ table) {
    int idx = blockIdx.x * blockDim.x + threadIdx.x;
    if (idx >= 4096) return;
    int rel = idx - 2048;
    int bucket = (rel > 0) ? 16 : 0;
    int ad = rel < 0 ? -rel : rel;
    int bb;
    if (ad < 8) {
        bb = ad;
    } else {
        float rp = (float)ad;
        float l  = (float)log((double)(rp / 8.0f));
        float v  = (l / 2.7725887f) * 8.0f;
        bb = 8 + (int)v;
        if (bb > 15) bb = 15;
    }
    bucket += bb;
    #pragma unroll
    for (int h = 0; h < NHEADS; h++)
        g_bias[h * 4096 + idx] = table[bucket * NHEADS + h];
}

// ---------------------------------------------------------------------------
// 2) position_bias output
// ---------------------------------------------------------------------------
__global__ void bias_write_kernel(float* __restrict__ out) {
    int q = blockIdx.x;
    int h = blockIdx.y;
    int k = threadIdx.x << 2;
    const float* src = g_bias + h * 4096 + (2048 - q) + k;
    float4 v = make_float4(src[0], src[1], src[2], src[3]);
    *(float4*)(out + ((size_t)h * SEQ + q) * SEQ + k) = v;
}

// ---------------------------------------------------------------------------
// 3a) hidden split
// ---------------------------------------------------------------------------
__global__ __launch_bounds__(256) void hsplit_kernel(const float* __restrict__ src) {
    size_t i = ((size_t)blockIdx.x * 256 + threadIdx.x) << 2;
    float4 v = *(const float4*)(src + i);
    float h0 = __half2float(__float2half_rn(v.x));
    float h1 = __half2float(__float2half_rn(v.y));
    float h2 = __half2float(__float2half_rn(v.z));
    float h3 = __half2float(__float2half_rn(v.w));
    *(uint2*)(g_hh + i) = make_uint2(packh2(v.x, v.y), packh2(v.z, v.w));
    *(uint2*)(g_hl + i) = make_uint2(packh2(v.x - h0, v.y - h1), packh2(v.z - h2, v.w - h3));
}

// ---------------------------------------------------------------------------
// 3b) weight transpose + split
// ---------------------------------------------------------------------------
__global__ __launch_bounds__(256) void wsplit_kernel(
    const float* __restrict__ w, __half* __restrict__ outh,
    __half* __restrict__ outl, int N)
{
    __shared__ float st[64][68];
    int tid = threadIdx.x;
    int n0 = blockIdx.x << 6, k0 = blockIdx.y << 6;
    #pragma unroll
    for (int j = 0; j < 4; j++) {
        int i = tid + (j << 8);
        int kr = i >> 4, nc = (i & 15) << 2;
        float4 v = *(const float4*)(w + (size_t)(k0 + kr) * N + n0 + nc);
        st[nc + 0][kr] = v.x;
        st[nc + 1][kr] = v.y;
        st[nc + 2][kr] = v.z;
        st[nc + 3][kr] = v.w;
    }
    __syncthreads();
    #pragma unroll
    for (int j = 0; j < 4; j++) {
        int i = tid + (j << 8);
        int nr = i >> 4, kc = (i & 15) << 2;
        float a = st[nr][kc], b = st[nr][kc + 1], c = st[nr][kc + 2], d = st[nr][kc + 3];
        float ha = __half2float(__float2half_rn(a));
        float hb = __half2float(__float2half_rn(b));
        float hc = __half2float(__float2half_rn(c));
        float hd = __half2float(__float2half_rn(d));
        size_t dst = (size_t)(n0 + nr) * DMODEL + k0 + kc;
        *(uint2*)(outh + dst) = make_uint2(packh2(a, b), packh2(c, d));
        *(uint2*)(outl + dst) = make_uint2(packh2(a - ha, b - hb), packh2(c - hc, d - hd));
    }
}

// ---------------------------------------------------------------------------
// 4) fp16x3 GEMM with cp.async double buffering (unchanged, proven)
// ---------------------------------------------------------------------------
#define GB_AH 0
#define GB_AL 16384
#define GB_BH 32768
#define GB_BL 40960
#define GB_STRIDE 49152
#define GS_TOT 98304

__global__ __launch_bounds__(256) void gemm_fp16x3_kernel(
    const __half* __restrict__ Ah, const __half* __restrict__ Al,
    const __half* __restrict__ Bh, const __half* __restrict__ Bl,
    float* __restrict__ C, int N, int K)
{
    extern __shared__ char sm[];
    uint32_t sb = smem_u32(sm);
    int tid = threadIdx.x, warp = tid >> 5, lane = tid & 31;
    int bn = blockIdx.x << 6, bm = blockIdx.y << 7;
    int wm = warp >> 1, wn = warp & 1;

    int arow_l = (lane & 15), ach = lane >> 4;
    int brlo = (lane & 7) + ((lane >> 4) << 3), bch = (lane >> 3) & 1;
    int g = lane >> 2, tg = lane & 3;

    float acc[2][4][4];
    #pragma unroll
    for (int mi = 0; mi < 2; mi++)
        #pragma unroll
        for (int nb = 0; nb < 4; nb++)
            #pragma unroll
            for (int e = 0; e < 4; e++) acc[mi][nb][e] = 0.f;

    {
        uint32_t dst = sb;
        #pragma unroll
        for (int j = 0; j < 4; j++) {
            int i = tid + (j << 8);
            int row = i >> 3, ch = i & 7;
            int off = (row << 7) + ((ch ^ (row & 7)) << 4);
            CP16(dst + GB_AH + off, Ah + (size_t)(bm + row) * K + (ch << 3));
            CP16(dst + GB_AL + off, Al + (size_t)(bm + row) * K + (ch << 3));
        }
        #pragma unroll
        for (int j = 0; j < 2; j++) {
            int i = tid + (j << 8);
            int row = i >> 3, ch = i & 7;
            int off = (row << 7) + ((ch ^ (row & 7)) << 4);
            CP16(dst + GB_BH + off, Bh + (size_t)(bn + row) * K + (ch << 3));
            CP16(dst + GB_BL + off, Bl + (size_t)(bn + row) * K + (ch << 3));
        }
        CP_COMMIT();
    }

    int buf = 0;
    int nchunks = K >> 6;
    for (int c = 0; c < nchunks; c++) {
        CP_WAIT0();
        __syncthreads();
        if (c + 1 < nchunks) {
            int k1 = (c + 1) << 6;
            uint32_t dst = sb + (buf ^ 1) * GB_STRIDE;
            #pragma unroll
            for (int j = 0; j < 4; j++) {
                int i = tid + (j << 8);
                int row = i >> 3, ch = i & 7;
                int off = (row << 7) + ((ch ^ (row & 7)) << 4);
                CP16(dst + GB_AH + off, Ah + (size_t)(bm + row) * K + k1 + (ch << 3));
                CP16(dst + GB_AL + off, Al + (size_t)(bm + row) * K + k1 + (ch << 3));
            }
            #pragma unroll
            for (int j = 0; j < 2; j++) {
                int i = tid + (j << 8);
                int row = i >> 3, ch = i & 7;
                int off = (row << 7) + ((ch ^ (row & 7)) << 4);
                CP16(dst + GB_BH + off, Bh + (size_t)(bn + row) * K + k1 + (ch << 3));
                CP16(dst + GB_BL + off, Bl + (size_t)(bn + row) * K + k1 + (ch << 3));
            }
            CP_COMMIT();
        }
        uint32_t base = sb + buf * GB_STRIDE;

        #pragma unroll
        for (int ks = 0; ks < 4; ks++) {
            uint32_t ah[2][4], al[2][4], bh4[2][4], bl4[2][4];
            #pragma unroll
            for (int mi = 0; mi < 2; mi++) {
                int arow = (wm << 5) + (mi << 4) + arow_l;
                uint32_t aoff = (uint32_t)(arow << 7) + ((((ks << 1) + ach) ^ (arow & 7)) << 4);
                ldsm4(ah[mi], base + GB_AH + aoff);
                ldsm4(al[mi], base + GB_AL + aoff);
            }
            #pragma unroll
            for (int np = 0; np < 2; np++) {
                int brow = (wn << 5) + (np << 4) + brlo;
                uint32_t boff = (uint32_t)(brow << 7) + ((((ks << 1) + bch) ^ (brow & 7)) << 4);
                ldsm4(bh4[np], base + GB_BH + boff);
                ldsm4(bl4[np], base + GB_BL + boff);
            }
            #pragma unroll
            for (int mi = 0; mi < 2; mi++)
                #pragma unroll
                for (int np = 0; np < 2; np++) {
                    mma_fp16(acc[mi][2 * np],     ah[mi], bh4[np]);
                    mma_fp16(acc[mi][2 * np],     al[mi], bh4[np]);
                    mma_fp16(acc[mi][2 * np],     ah[mi], bl4[np]);
                    mma_fp16(acc[mi][2 * np + 1], ah[mi], bh4[np] + 2);
                    mma_fp16(acc[mi][2 * np + 1], al[mi], bh4[np] + 2);
                    mma_fp16(acc[mi][2 * np + 1], ah[mi], bl4[np] + 2);
                }
        }
        buf ^= 1;
    }

    #pragma unroll
    for (int mi = 0; mi < 2; mi++) {
        int r = bm + (wm << 5) + (mi << 4) + g;
        #pragma unroll
        for (int nb = 0; nb < 4; nb++) {
            int c = bn + (wn << 5) + (nb << 3) + (tg << 1);
            *(float2*)&C[(size_t)r * N + c]       = make_float2(acc[mi][nb][0], acc[mi][nb][1]);
            *(float2*)&C[(size_t)(r + 8) * N + c] = make_float2(acc[mi][nb][2], acc[mi][nb][3]);
        }
    }
}

// ---------------------------------------------------------------------------
// 5) Prep: split Q,K fp16 hi/lo; V transposed hi/lo
// ---------------------------------------------------------------------------
__global__ __launch_bounds__(256) void prep_kernel() {
    __shared__ __half vh_s[64][68], vl_s[64][68];
    int tid = threadIdx.x;
    int st = blockIdx.x, h = blockIdx.y, b = blockIdx.z;
    int s0 = st << 6;
    int bh = b * NHEADS + h;

    #pragma unroll
    for (int j = 0; j < 4; j++) {
        int i = tid + (j << 8);
        int row = i >> 4, d4 = (i & 15) << 2;
        const float* base = g_qkv + (size_t)(b * SEQ + s0 + row) * QKV3 + h * DHEAD + d4;
        float4 qv = *(const float4*)base;
        float4 kv = *(const float4*)(base + INNER);
        float4 vv = *(const float4*)(base + 2 * INNER);
        size_t dst = (size_t)(bh * SEQ + s0 + row) * DHEAD + d4;
        float q0h = __half2float(__float2half_rn(qv.x));
        float q1h = __half2float(__float2half_rn(qv.y));
        float q2h = __half2float(__float2half_rn(qv.z));
        float q3h = __half2float(__float2half_rn(qv.w));
        *(uint2*)(g_qh + dst) = make_uint2(packh2(qv.x, qv.y), packh2(qv.z, qv.w));
        *(uint2*)(g_ql + dst) = make_uint2(packh2(qv.x - q0h, qv.y - q1h), packh2(qv.z - q2h, qv.w - q3h));
        float k0h = __half2float(__float2half_rn(kv.x));
        float k1h = __half2float(__float2half_rn(kv.y));
        float k2h = __half2float(__float2half_rn(kv.z));
        float k3h = __half2float(__float2half_rn(kv.w));
        *(uint2*)(g_kh + dst) = make_uint2(packh2(kv.x, kv.y), packh2(kv.z, kv.w));
        *(uint2*)(g_kl + dst) = make_uint2(packh2(kv.x - k0h, kv.y - k1h), packh2(kv.z - k2h, kv.w - k3h));
        float v0h = __half2float(__float2half_rn(vv.x));
        float v1h = __half2float(__float2half_rn(vv.y));
        float v2h = __half2float(__float2half_rn(vv.z));
        float v3h = __half2float(__float2half_rn(vv.w));
        vh_s[row][d4 + 0] = __float2half_rn(vv.x);
        vh_s[row][d4 + 1] = __float2half_rn(vv.y);
        vh_s[row][d4 + 2] = __float2half_rn(vv.z);
        vh_s[row][d4 + 3] = __float2half_rn(vv.w);
        vl_s[row][d4 + 0] = __float2half_rn(vv.x - v0h);
        vl_s[row][d4 + 1] = __float2half_rn(vv.y - v1h);
        vl_s[row][d4 + 2] = __float2half_rn(vv.z - v2h);
        vl_s[row][d4 + 3] = __float2half_rn(vv.w - v3h);
    }
    __syncthreads();
    #pragma unroll
    for (int j = 0; j < 4; j++) {
        int i = tid + (j << 8);
        int drow = i >> 4, s4 = (i & 15) << 2;
        size_t dst = (size_t)(bh * DHEAD + drow) * SEQ + s0 + s4;
        __half2 h0 = __halves2half2(vh_s[s4 + 0][drow], vh_s[s4 + 1][drow]);
        __half2 h1 = __halves2half2(vh_s[s4 + 2][drow], vh_s[s4 + 3][drow]);
        *(uint2*)(g_vth + dst) = make_uint2(*(uint32_t*)&h0, *(uint32_t*)&h1);
        __half2 l0 = __halves2half2(vl_s[s4 + 0][drow], vl_s[s4 + 1][drow]);
        __half2 l1 = __halves2half2(vl_s[s4 + 2][drow], vl_s[s4 + 3][drow]);
        *(uint2*)(g_vtl + dst) = make_uint2(*(uint32_t*)&l0, *(uint32_t*)&l1);
    }
}

// ---------------------------------------------------------------------------
// 6) fp16 flash attention, cp.async double-buffered K/V, 2 CTAs/SM
//    Register diet: P packed IN PLACE into S storage; l-sum deferred to epilogue
// ---------------------------------------------------------------------------
#define SM_QH 0
#define SM_QL 16384
#define SM_KV 32768
#define KV_KH 0
#define KV_KL 8192
#define KV_VH 16384
#define KV_VL 24576
#define KV_STRIDE 32768
#define SM_TOT 98304

__device__ __forceinline__ void prefetch_kv(uint32_t dst, int bh, int k0, int tid) {
    const __half* kh  = g_kh  + ((size_t)bh * SEQ + k0) * DHEAD;
    const __half* kl  = g_kl  + ((size_t)bh * SEQ + k0) * DHEAD;
    const __half* vth = g_vth + (size_t)bh * DHEAD * SEQ + k0;
    const __half* vtl = g_vtl + (size_t)bh * DHEAD * SEQ + k0;
    #pragma unroll
    for (int j = 0; j < 2; j++) {
        int i = tid + (j << 8);
        int row = i >> 3, ch = i & 7;
        int off = (row << 7) + ((ch ^ (row & 7)) << 4);
        CP16(dst + KV_KH + off, kh  + (size_t)row * DHEAD + (ch << 3));
        CP16(dst + KV_KL + off, kl  + (size_t)row * DHEAD + (ch << 3));
        CP16(dst + KV_VH + off, vth + (size_t)row * SEQ   + (ch << 3));
        CP16(dst + KV_VL + off, vtl + (size_t)row * SEQ   + (ch << 3));
    }
}

__global__ __launch_bounds__(256, 2) void attn_mma_kernel() {
    extern __shared__ char sm[];
    uint32_t sb = smem_u32(sm);
    int tid = threadIdx.x, warp = tid >> 5, lane = tid & 31;
    int qt = blockIdx.x, h = blockIdx.y, b = blockIdx.z;
    int q0 = qt << 7, bh = b * NHEADS + h;

    {
        const __half* qh = g_qh + (size_t)(bh * SEQ + q0) * DHEAD;
        const __half* ql = g_ql + (size_t)(bh * SEQ + q0) * DHEAD;
        #pragma unroll
        for (int j = 0; j < 4; j++) {
            int i = tid + (j << 8);
            int row = i >> 3, ch = i & 7;
            int off = (row << 7) + ((ch ^ (row & 7)) << 4);
            *(uint4*)(sm + SM_QH + off) = *(const uint4*)(qh + (size_t)row * DHEAD + (ch << 3));
            *(uint4*)(sm + SM_QL + off) = *(const uint4*)(ql + (size_t)row * DHEAD + (ch << 3));
        }
    }
    prefetch_kv(sb + SM_KV, bh, 0, tid);
    CP_COMMIT();

    int g = lane >> 2, tg = lane & 3;
    int rw = warp << 4;
    int r0 = rw + g;
    int arow = rw + (lane & 7) + (((lane >> 3) & 1) << 3);
    int ach  = (lane >> 4);
    int asw  = arow & 7;
    uint32_t abase = (uint32_t)(arow << 7);
    int brlo = (lane & 7) + ((lane >> 4) << 3);
    int bch  = (lane >> 3) & 1;

    const float* gb2 = g_bias + h * 4096 + 2048 - q0;
    float O[8][4];
    #pragma unroll
    for (int nd = 0; nd < 8; nd++)
        #pragma unroll
        for (int e = 0; e < 4; e++) O[nd][e] = 0.f;
    float m0r = -1e30f, m1r = -1e30f, l0 = 0.f, l1 = 0.f;  // l0,l1: per-thread partial

    int buf = 0;
    for (int kb = 0; kb < 32; kb++) {
        int k0 = kb << 6;
        CP_WAIT0();
        __syncthreads();
        if (kb < 31) {
            prefetch_kv(sb + SM_KV + (buf ^ 1) * KV_STRIDE, bh, k0 + 64, tid);
            CP_COMMIT();
        }
        uint32_t kvb = sb + SM_KV + buf * KV_STRIDE;

        float S[8][4];
        uint32_t* Su = (uint32_t*)S;   // in-place P packing target
        #pragma unroll
        for (int nt = 0; nt < 8; nt++)
            #pragma unroll
            for (int e = 0; e < 4; e++) S[nt][e] = 0.f;

        #pragma unroll
        for (int ks = 0; ks < 4; ks++) {
            uint32_t qhf[4], qlf[4];
            uint32_t aoff = abase + ((((ks << 1) + ach) ^ asw) << 4);
            ldsm4(qhf, sb + SM_QH + aoff);
            ldsm4(qlf, sb + SM_QL + aoff);
            #pragma unroll
            for (int np = 0; np < 4; np++) {
                int brow = (np << 4) + brlo;
                uint32_t boff = (uint32_t)(brow << 7) + ((((ks << 1) + bch) ^ (brow & 7)) << 4);
                uint32_t kh4[4], kl4[4];
                ldsm4(kh4, kvb + KV_KH + boff);
                ldsm4(kl4, kvb + KV_KL + boff);
                mma_fp16(S[2 * np],     qhf, kh4);
                mma_fp16(S[2 * np],     qlf, kh4);
                mma_fp16(S[2 * np],     qhf, kl4);
                mma_fp16(S[2 * np + 1], qhf, kh4 + 2);
                mma_fp16(S[2 * np + 1], qlf, kh4 + 2);
                mma_fp16(S[2 * np + 1], qhf, kl4 + 2);
            }
        }

        // bias + row max (shuffles across the 4 tg lanes)
        float ml0 = -1e30f, ml1 = -1e30f;
        #pragma unroll
        for (int nt = 0; nt < 8; nt++) {
            int c = k0 + (nt << 3) + (tg << 1);
            S[nt][0] += __ldg(gb2 + c - r0);
            S[nt][1] += __ldg(gb2 + c + 1 - r0);
            S[nt][2] += __ldg(gb2 + c - r0 - 8);
            S[nt][3] += __ldg(gb2 + c + 1 - r0 - 8);
            ml0 = fmaxf(ml0, fmaxf(S[nt][0], S[nt][1]));
            ml1 = fmaxf(ml1, fmaxf(S[nt][2], S[nt][3]));
        }
        ml0 = fmaxf(ml0, __shfl_xor_sync(0xffffffffu, ml0, 1));
        ml0 = fmaxf(ml0, __shfl_xor_sync(0xffffffffu, ml0, 2));
        ml1 = fmaxf(ml1, __shfl_xor_sync(0xffffffffu, ml1, 1));
        ml1 = fmaxf(ml1, __shfl_xor_sync(0xffffffffu, ml1, 2));
        float mn0 = fmaxf(m0r, ml0), mn1 = fmaxf(m1r, ml1);
        float sc0 = fexp(m0r - mn0), sc1 = fexp(m1r - mn1);
        m0r = mn0; m1r = mn1;

        // exp + per-thread partial l (no shuffles) + in-place split to fp16 h/l
        float rs0 = 0.f, rs1 = 0.f;
        #pragma unroll
        for (int nt = 0; nt < 8; nt++) {
            float a0 = fexp(S[nt][0] - mn0);
            float a1 = fexp(S[nt][1] - mn0);
            float a2 = fexp(S[nt][2] - mn1);
            float a3 = fexp(S[nt][3] - mn1);
            rs0 += a0 + a1;
            rs1 += a2 + a3;
            float h0f = __half2float(__float2half_rn(a0));
            float h1f = __half2float(__float2half_rn(a1));
            float h2f = __half2float(__float2half_rn(a2));
            float h3f = __half2float(__float2half_rn(a3));
            // layout: word0 = hi(a0,a1), word1 = hi(a2,a3), word2 = lo(a0,a1), word3 = lo(a2,a3)
            Su[nt * 4 + 0] = packh2(a0, a1);
            Su[nt * 4 + 1] = packh2(a2, a3);
            Su[nt * 4 + 2] = packh2(a0 - h0f, a1 - h1f);
            Su[nt * 4 + 3] = packh2(a2 - h2f, a3 - h3f);
        }
        l0 = l0 * sc0 + rs0;
        l1 = l1 * sc1 + rs1;
        #pragma unroll
        for (int nd = 0; nd < 8; nd++) {
            O[nd][0] *= sc0; O[nd][1] *= sc0;
            O[nd][2] *= sc1; O[nd][3] *= sc1;
        }

        // O += P V, P read from packed S storage
        // A-frag for kstep ks: rows=q, k=16ks..16ks+15 -> nt = 2ks (cols 0..7), 2ks+1 (cols 8..15)
        #pragma unroll
        for (int ks = 0; ks < 4; ks++) {
            uint32_t ph0 = Su[(2 * ks) * 4 + 0], ph1 = Su[(2 * ks) * 4 + 1];
            uint32_t ph2 = Su[(2 * ks + 1) * 4 + 0], ph3 = Su[(2 * ks + 1) * 4 + 1];
            uint32_t pl0 = Su[(2 * ks) * 4 + 2], pl1 = Su[(2 * ks) * 4 + 3];
            uint32_t pl2 = Su[(2 * ks + 1) * 4 + 2], pl3 = Su[(2 * ks + 1) * 4 + 3];
            #pragma unroll
            for (int np = 0; np < 4; np++) {
                int brow = (np << 4) + brlo;
                uint32_t boff = (uint32_t)(brow << 7) + ((((ks << 1) + bch) ^ (brow & 7)) << 4);
                uint32_t vh4[4], vl4[4];
                ldsm4(vh4, kvb + KV_VH + boff);
                ldsm4(vl4, kvb + KV_VL + boff);
                mma_fp16_e(O[2 * np],     ph0, ph1, ph2, ph3, vh4[0], vh4[1]);
                mma_fp16_e(O[2 * np],     pl0, pl1, pl2, pl3, vh4[0], vh4[1]);
                mma_fp16_e(O[2 * np],     ph0, ph1, ph2, ph3, vl4[0], vl4[1]);
                mma_fp16_e(O[2 * np + 1], ph0, ph1, ph2, ph3, vh4[2], vh4[3]);
                mma_fp16_e(O[2 * np + 1], pl0, pl1, pl2, pl3, vh4[2], vh4[3]);
                mma_fp16_e(O[2 * np + 1], ph0, ph1, ph2, ph3, vl4[2], vl4[3]);
            }
        }
        buf ^= 1;
    }

    // epilogue: reduce partial l across tg lanes, normalize, store split
    l0 += __shfl_xor_sync(0xffffffffu, l0, 1);
    l0 += __shfl_xor_sync(0xffffffffu, l0, 2);
    l1 += __shfl_xor_sync(0xffffffffu, l1, 1);
    l1 += __shfl_xor_sync(0xffffffffu, l1, 2);
    float i0 = 1.f / l0, i1 = 1.f / l1;
    size_t base0 = ((size_t)b * SEQ + q0 + r0) * INNER + h * DHEAD + (tg << 1);
    size_t base1 = base0 + 8 * INNER;
    #pragma unroll
    for (int nd = 0; nd < 8; nd++) {
        float x0 = O[nd][0] * i0, x1 = O[nd][1] * i0;
        float y0 = O[nd][2] * i1, y1 = O[nd][3] * i1;
        float xh0 = __half2float(__float2half_rn(x0));
        float xh1 = __half2float(__float2half_rn(x1));
        float yh0 = __half2float(__float2half_rn(y0));
        float yh1 = __half2float(__float2half_rn(y1));
        *(uint32_t*)(g_aih + base0 + (nd << 3)) = packh2(x0, x1);
        *(uint32_t*)(g_ail + base0 + (nd << 3)) = packh2(x0 - xh0, x1 - xh1);
        *(uint32_t*)(g_aih + base1 + (nd << 3)) = packh2(y0, y1);
        *(uint32_t*)(g_ail + base1 + (nd << 3)) = packh2(y0 - yh0, y1 - yh1);
    }
}

// ---------------------------------------------------------------------------
extern "C" void kernel_launch(void* const* d_in, const int* in_sizes, int n_in,
                              void* d_out, int out_size)
{
    const float* hidden = (const float*)d_in[0];
    const float* w_qkv  = (const float*)d_in[1];
    const float* w_o    = (const float*)d_in[2];
    const float* table  = (const float*)d_in[3];
    float* out = (float*)d_out;

    float* qkv_ptr = nullptr;
    __half *hh, *hl, *wqh, *wql, *woh, *wol, *aih, *ail;
    cudaGetSymbolAddress((void**)&qkv_ptr, g_qkv);
    cudaGetSymbolAddress((void**)&hh,  g_hh);
    cudaGetSymbolAddress((void**)&hl,  g_hl);
    cudaGetSymbolAddress((void**)&wqh, g_wqh);
    cudaGetSymbolAddress((void**)&wql, g_wql);
    cudaGetSymbolAddress((void**)&woh, g_woh);
    cudaGetSymbolAddress((void**)&wol, g_wol);
    cudaGetSymbolAddress((void**)&aih, g_aih);
    cudaGetSymbolAddress((void**)&ail, g_ail);

    cudaFuncSetAttribute(attn_mma_kernel,
                         cudaFuncAttributeMaxDynamicSharedMemorySize, SM_TOT);
    cudaFuncSetAttribute(gemm_fp16x3_kernel,
                         cudaFuncAttributeMaxDynamicSharedMemorySize, GS_TOT);

    bias_fill_kernel<<<16, 256>>>(table);
    bias_write_kernel<<<dim3(SEQ, NHEADS), 512>>>(out + (size_t)BATCH * SEQ * DMODEL);
    hsplit_kernel<<<(BATCH * SEQ * DMODEL) / 1024, 256>>>(hidden);
    wsplit_kernel<<<dim3(QKV3 / 64, DMODEL / 64), 256>>>(w_qkv, wqh, wql, QKV3);
    wsplit_kernel<<<dim3(INNER / 64, DMODEL / 64), 256>>>(w_o, woh, wol, INNER);
    gemm_fp16x3_kernel<<<dim3(QKV3 / 64, (BATCH * SEQ) / 128), 256, GS_TOT>>>(
        hh, hl, wqh, wql, qkv_ptr, QKV3, DMODEL);
    prep_kernel<<<dim3(32, NHEADS, BATCH), 256>>>();
    attn_mma_kernel<<<dim3(16, NHEADS, BATCH), 256, SM_TOT>>>();
    gemm_fp16x3_kernel<<<dim3(DMODEL / 64, (BATCH * SEQ) / 128), 256, GS_TOT>>>(
        aih, ail, woh, wol, out, DMODEL, INNER);
}